// round 1
// baseline (speedup 1.0000x reference)
#include <cuda_runtime.h>

// Shapes are fixed by the problem: B=4, N=4096, D=1024, H=16, d_head=64.
#define BB 4
#define NN 4096
#define DD 1024
#define HH 16
#define DH 64
#define NSPLIT 8
// s = (d_head^0.5)^(-0.25) = 8^(-0.25) = 2^(-0.75)
#define SCALE 0.5946035575013605f

// Scratch (no cudaMalloc allowed): ~227 MB of __device__ globals.
__device__ float g_Q [(size_t)BB * NN * DD];            // Q proj -> row-softmaxed Qs (in place)
__device__ float g_V [(size_t)BB * NN * DD];            // V proj
__device__ float g_Km[(size_t)BB * NN * DD];            // column-softmax of Qs
__device__ float g_ctx[(size_t)NSPLIT * BB * HH * DH * DH]; // split-K partials of K^T V
__device__ float g_M [(size_t)BB * DD * DD];            // Mbig = blockdiag(ctx) @ Wo

// ---------------------------------------------------------------------------
// Generic tiled SGEMM: C[b] = A[b] @ B[b] + bias, row-major, 128x128x8 tiles,
// 256 threads, 8x8 per thread, double-buffered smem. All dims divide evenly.
// ---------------------------------------------------------------------------
__global__ void __launch_bounds__(256) sgemm_bias(
    const float* __restrict__ A, const float* __restrict__ Bm,
    const float* __restrict__ bias, float* __restrict__ C,
    int M, int N, int K,
    long long sA, long long sB, long long sC)
{
    const int b = blockIdx.z;
    A  += (long long)b * sA;
    Bm += (long long)b * sB;
    C  += (long long)b * sC;

    const int tid  = threadIdx.x;
    const int row0 = blockIdx.y * 128;
    const int col0 = blockIdx.x * 128;

    __shared__ float As[2][8][128];
    __shared__ float Bs[2][8][128];

    const int la_r = tid >> 1;            // A tile row 0..127
    const int la_k = (tid & 1) << 2;      // A tile k 0 or 4
    const int lb_k = tid >> 5;            // B tile k 0..7
    const int lb_c = (tid & 31) << 2;     // B tile col 0..124

    const int tr = (tid >> 4) << 3;       // compute rows
    const int tc = (tid & 15) << 3;       // compute cols

    const float* Ap = A  + (long long)(row0 + la_r) * K + la_k;
    const float* Bp = Bm + (long long)lb_k * N + col0 + lb_c;

    float acc[8][8];
    #pragma unroll
    for (int i = 0; i < 8; i++)
        #pragma unroll
        for (int j = 0; j < 8; j++) acc[i][j] = 0.f;

    float4 a4 = *(const float4*)Ap;
    float4 b4 = *(const float4*)Bp;
    int buf = 0;
    As[0][la_k + 0][la_r] = a4.x; As[0][la_k + 1][la_r] = a4.y;
    As[0][la_k + 2][la_r] = a4.z; As[0][la_k + 3][la_r] = a4.w;
    *(float4*)&Bs[0][lb_k][lb_c] = b4;
    __syncthreads();

    const int nk = K >> 3;
    for (int t = 0; t < nk; t++) {
        if (t + 1 < nk) {
            a4 = *(const float4*)(Ap + (t + 1) * 8);
            b4 = *(const float4*)(Bp + (long long)(t + 1) * 8 * N);
        }
        #pragma unroll
        for (int k = 0; k < 8; k++) {
            float ar[8], br[8];
            *(float4*)(ar)     = *(float4*)&As[buf][k][tr];
            *(float4*)(ar + 4) = *(float4*)&As[buf][k][tr + 4];
            *(float4*)(br)     = *(float4*)&Bs[buf][k][tc];
            *(float4*)(br + 4) = *(float4*)&Bs[buf][k][tc + 4];
            #pragma unroll
            for (int i = 0; i < 8; i++)
                #pragma unroll
                for (int j = 0; j < 8; j++)
                    acc[i][j] = fmaf(ar[i], br[j], acc[i][j]);
        }
        if (t + 1 < nk) {
            buf ^= 1;
            As[buf][la_k + 0][la_r] = a4.x; As[buf][la_k + 1][la_r] = a4.y;
            As[buf][la_k + 2][la_r] = a4.z; As[buf][la_k + 3][la_r] = a4.w;
            *(float4*)&Bs[buf][lb_k][lb_c] = b4;
            __syncthreads();
        }
    }

    #pragma unroll
    for (int i = 0; i < 8; i++) {
        float* Cp = C + (long long)(row0 + tr + i) * N + col0 + tc;
        #pragma unroll
        for (int j = 0; j < 8; j += 4) {
            float4 o;
            o.x = acc[i][j + 0] + bias[col0 + tc + j + 0];
            o.y = acc[i][j + 1] + bias[col0 + tc + j + 1];
            o.z = acc[i][j + 2] + bias[col0 + tc + j + 2];
            o.w = acc[i][j + 3] + bias[col0 + tc + j + 3];
            *(float4*)(Cp + j) = o;
        }
    }
}

// ---------------------------------------------------------------------------
// Row softmax over d_head=64 (contiguous), in place on g_Q, times SCALE.
// One warp per row, 2 elems per lane.
// ---------------------------------------------------------------------------
__global__ void __launch_bounds__(256) row_softmax()
{
    const size_t row = (size_t)blockIdx.x * 8 + (threadIdx.x >> 5);
    const int lane = threadIdx.x & 31;
    float* p = g_Q + row * DH + lane * 2;
    float2 v = *(float2*)p;
    float m = fmaxf(v.x, v.y);
    #pragma unroll
    for (int o = 16; o; o >>= 1) m = fmaxf(m, __shfl_xor_sync(0xffffffffu, m, o));
    float e0 = __expf(v.x - m), e1 = __expf(v.y - m);
    float s = e0 + e1;
    #pragma unroll
    for (int o = 16; o; o >>= 1) s += __shfl_xor_sync(0xffffffffu, s, o);
    float inv = SCALE / s;
    float2 o2 = {e0 * inv, e1 * inv};
    *(float2*)p = o2;
}

// ---------------------------------------------------------------------------
// Column softmax over the sequence dim N (axis -2), per (b, column).
// Block = 512 threads = 32 columns x 16 row-strides; deterministic reduce.
// ---------------------------------------------------------------------------
__global__ void __launch_bounds__(512) col_softmax()
{
    const int b  = blockIdx.y;
    const int cl = threadIdx.x & 31;
    const int c  = (blockIdx.x << 5) + cl;
    const int r  = threadIdx.x >> 5;           // 0..15
    const float* src = g_Q  + (size_t)b * NN * DD + c;
    float*       dst = g_Km + (size_t)b * NN * DD + c;

    __shared__ float red[16][32];

    float m = -1e30f;
    for (int n = r; n < NN; n += 16)
        m = fmaxf(m, src[(size_t)n * DD]);
    red[r][cl] = m;
    __syncthreads();
    m = red[0][cl];
    #pragma unroll
    for (int i = 1; i < 16; i++) m = fmaxf(m, red[i][cl]);
    __syncthreads();

    float s = 0.f;
    for (int n = r; n < NN; n += 16)
        s += __expf(src[(size_t)n * DD] - m);
    red[r][cl] = s;
    __syncthreads();
    s = 0.f;
    #pragma unroll
    for (int i = 0; i < 16; i++) s += red[i][cl];

    const float inv = SCALE / s;
    for (int n = r; n < NN; n += 16)
        dst[(size_t)n * DD] = __expf(src[(size_t)n * DD] - m) * inv;
}

// ---------------------------------------------------------------------------
// ctx partials: g_ctx[sp][bh][d][e] = sum over n-slice of Km[n,d] * V[n,e].
// Grid (B*H, NSPLIT), 256 threads, 4x4 per thread. No atomics (deterministic).
// ---------------------------------------------------------------------------
__global__ void __launch_bounds__(256) ctx_kernel()
{
    const int bh = blockIdx.x, b = bh >> 4, h = bh & 15;
    const int n0 = blockIdx.y * (NN / NSPLIT);
    const float* Kp = g_Km + (size_t)b * NN * DD + h * DH;
    const float* Vp = g_V  + (size_t)b * NN * DD + h * DH;

    __shared__ float Ks[8][64], Vs[8][64];
    const int tid = threadIdx.x;
    const int lr = tid >> 5, lc = (tid & 31) << 1;
    const int rd = (tid >> 4) << 2, ce = (tid & 15) << 2;

    float acc[4][4] = {};
    for (int nk = 0; nk < NN / NSPLIT; nk += 8) {
        const size_t off = (size_t)(n0 + nk + lr) * DD + lc;
        *(float2*)&Ks[lr][lc] = *(const float2*)(Kp + off);
        *(float2*)&Vs[lr][lc] = *(const float2*)(Vp + off);
        __syncthreads();
        #pragma unroll
        for (int k = 0; k < 8; k++) {
            float a[4], v[4];
            *(float4*)a = *(float4*)&Ks[k][rd];
            *(float4*)v = *(float4*)&Vs[k][ce];
            #pragma unroll
            for (int i = 0; i < 4; i++)
                #pragma unroll
                for (int j = 0; j < 4; j++)
                    acc[i][j] = fmaf(a[i], v[j], acc[i][j]);
        }
        __syncthreads();
    }
    float* o = g_ctx + (((size_t)blockIdx.y * (BB * HH) + bh) << 12);
    #pragma unroll
    for (int i = 0; i < 4; i++) {
        float4 t = {acc[i][0], acc[i][1], acc[i][2], acc[i][3]};
        *(float4*)(o + (rd + i) * 64 + ce) = t;
    }
}

// ---------------------------------------------------------------------------
// Mbig[b][h*64+d][c] = sum_e ctx[b,h][d][e] * Wo[h*64+e][c]
// (sums the NSPLIT ctx partials on the fly). Grid (B*H, D/64), 256 threads.
// ---------------------------------------------------------------------------
__global__ void __launch_bounds__(256) mbig_kernel(const float* __restrict__ Wo)
{
    const int bh = blockIdx.x, b = bh >> 4, h = bh & 15;
    const int c0 = blockIdx.y << 6;

    __shared__ float cs[64][64];
    __shared__ float ws[64][64];
    const int tid = threadIdx.x;

    for (int i = tid; i < 4096; i += 256) {
        float sum = 0.f;
        #pragma unroll
        for (int sp = 0; sp < NSPLIT; sp++)
            sum += g_ctx[(((size_t)sp * (BB * HH) + bh) << 12) + i];
        cs[i >> 6][i & 63] = sum;
    }
    for (int i = tid; i < 1024; i += 256) {     // 64 rows x 16 float4
        int rr = i >> 4, cc = (i & 15) << 2;
        *(float4*)&ws[rr][cc] =
            *(const float4*)(Wo + (size_t)(h * DH + rr) * DD + c0 + cc);
    }
    __syncthreads();

    const int r0 = (tid >> 4) << 2, cc0 = (tid & 15) << 2;
    float acc[4][4] = {};
    #pragma unroll 16
    for (int k = 0; k < 64; k++) {
        float a[4], w[4];
        #pragma unroll
        for (int i = 0; i < 4; i++) a[i] = cs[r0 + i][k];
        *(float4*)w = *(float4*)&ws[k][cc0];
        #pragma unroll
        for (int i = 0; i < 4; i++)
            #pragma unroll
            for (int j = 0; j < 4; j++)
                acc[i][j] = fmaf(a[i], w[j], acc[i][j]);
    }
    float* out = g_M + ((size_t)b << 20) + (size_t)(h * DH + r0) * DD + c0 + cc0;
    #pragma unroll
    for (int i = 0; i < 4; i++) {
        float4 t = {acc[i][0], acc[i][1], acc[i][2], acc[i][3]};
        *(float4*)(out + (size_t)i * DD) = t;
    }
}

// ---------------------------------------------------------------------------
// Launcher.  Inputs: 0:x 1:Wq 2:bq 3:Wk(dead) 4:bk(dead) 5:Wv 6:bv 7:Wo 8:bo
// ---------------------------------------------------------------------------
extern "C" void kernel_launch(void* const* d_in, const int* in_sizes, int n_in,
                              void* d_out, int out_size)
{
    const float* x  = (const float*)d_in[0];
    const float* Wq = (const float*)d_in[1];
    const float* bq = (const float*)d_in[2];
    const float* Wv = (const float*)d_in[5];
    const float* bv = (const float*)d_in[6];
    const float* Wo = (const float*)d_in[7];
    const float* bo = (const float*)d_in[8];
    float* out = (float*)d_out;

    float *Q, *V, *Mb;
    cudaGetSymbolAddress((void**)&Q,  g_Q);
    cudaGetSymbolAddress((void**)&V,  g_V);
    cudaGetSymbolAddress((void**)&Mb, g_M);

    const long long sXD = (long long)NN * DD;
    dim3 gemm_grid(DD / 128, NN / 128, BB);

    // Q = x@Wq + bq ; V = x@Wv + bv  (x@Wk is dead code in the reference)
    sgemm_bias<<<gemm_grid, 256>>>(x, Wq, bq, Q, NN, DD, DD, sXD, 0, sXD);
    sgemm_bias<<<gemm_grid, 256>>>(x, Wv, bv, V, NN, DD, DD, sXD, 0, sXD);

    // Qs = softmax(Q, d_head) * s (in place)
    row_softmax<<<(BB * NN * HH) / 8, 256>>>();

    // Km = softmax(Qs, seq) * s
    col_softmax<<<dim3(DD / 32, BB), 512>>>();

    // ctx partials, then Mbig = ctx @ Wo (per head, fused partial-sum)
    ctx_kernel<<<dim3(BB * HH, NSPLIT), 256>>>();
    mbig_kernel<<<dim3(BB * HH, DD / 64), 256>>>(Wo);

    // out[b] = Qs[b] @ Mbig[b] + bo   (absorbs attn@Wo, skips attn buffer)
    sgemm_bias<<<gemm_grid, 256>>>(Q, Mb, bo, out, NN, DD, DD,
                                   sXD, (long long)DD * DD, sXD);
}

// round 4
// speedup vs baseline: 2.7089x; 2.7089x over previous
#include <cuda_runtime.h>
#include <cstdint>

// Shapes fixed: B=4, N=4096, D=1024, H=16, d_head=64.
#define BB 4
#define NN 4096
#define DD 1024
#define HH 16
#define DH 64
#define NSPLIT 8
#define SCALE 0.5946035575013605f   // (d_head^0.5)^(-0.25) = 2^(-0.75)

// Scratch (__device__ globals; no cudaMalloc allowed).
__device__ float g_Q  [(size_t)BB * NN * DD];   // Q proj -> row-softmaxed Qs (in place)
__device__ float g_V  [(size_t)BB * NN * DD];   // V proj
__device__ float g_Km [(size_t)BB * NN * DD];   // column-softmax of Qs
__device__ float g_ctx[(size_t)NSPLIT * BB * HH * DH * DH];
__device__ float g_Mt [(size_t)BB * DD * DD];   // Mbig^T per batch (n-major rows, k contiguous)
__device__ float g_WqT[(size_t)DD * DD];        // Wq^T
__device__ float g_WvT[(size_t)DD * DD];        // Wv^T

// ---------------------------------------------------------------------------
// fp32 -> tf32 (round to nearest) as raw bits
// ---------------------------------------------------------------------------
__device__ __forceinline__ uint32_t f2tf(float f) {
    uint32_t u;
    asm("cvt.rna.tf32.f32 %0, %1;" : "=r"(u) : "f"(f));
    return u;
}

// ---------------------------------------------------------------------------
// mma.sync tf32 GEMM (target-portable; tcgen05 is rejected by this harness's
// compute_103 PTX stage).  C[b] = A[b] @ Bt[b]^T + bias.
//   A  row-major [M, 1024]
//   Bt row-major [1024, 1024], row = output col n, col = k  (== col-major B)
// CTA tile 128x128, K-chunk 32. 8 warps as 2(m) x 4(n); warp tile 64x32.
// SMEM holds tiles in *fragment-major* order with an XOR-ks swizzle:
//   A frag (ks,mf): thread lane's 4 regs contiguous at block*128 + ((lane^ks)<<2)
//   B frag (ks,nf): thread lane's 2 regs contiguous at block*64  + ((lane^ks)<<1)
// so compute does pure LDS.128 / LDS.64, conflict-free.
// ---------------------------------------------------------------------------
#define GEMM_SMEM 65536   // 2 buffers x (A 16KB + B 16KB)

__global__ void __launch_bounds__(256)
gemm_mma(const float* __restrict__ A, const float* __restrict__ Bt,
         const float* __restrict__ bias, float* __restrict__ C,
         long long sA, long long sB, long long sC)
{
    extern __shared__ float smem[];
    uint32_t* As = (uint32_t*)smem;           // [2][4096]
    uint32_t* Bs = (uint32_t*)(smem + 8192);  // [2][4096]

    const int b = blockIdx.z;
    A  += (long long)b * sA;
    Bt += (long long)b * sB;
    C  += (long long)b * sC;

    const int n0 = blockIdx.x << 7;
    const int m0 = blockIdx.y << 7;
    const int tid  = threadIdx.x;
    const int lane = tid & 31;
    const int wid  = tid >> 5;
    const int wm   = wid >> 2;       // 0..1
    const int wn   = wid & 3;        // 0..3

    float acc[4][4][4];
    #pragma unroll
    for (int i = 0; i < 4; i++)
        #pragma unroll
        for (int j = 0; j < 4; j++)
            #pragma unroll
            for (int r = 0; r < 4; r++) acc[i][j][r] = 0.f;

    // Per-thread loader coordinates (4 float4 each for A and B per chunk).
    // q = s*256 + tid; r = q>>3 (tile row), c4 = (q&7)*4 (k offset).
    float4 pa[4], pb[4];

    auto loadg = [&](int t) {
        const int k0 = t << 5;
        #pragma unroll
        for (int s = 0; s < 4; s++) {
            const int q  = (s << 8) + tid;
            const int r  = q >> 3;
            const int c4 = (q & 7) << 2;
            pa[s] = *(const float4*)(A  + (long long)(m0 + r) * DD + k0 + c4);
            pb[s] = *(const float4*)(Bt + (long long)(n0 + r) * DD + k0 + c4);
        }
    };

    auto stores = [&](int buf) {
        #pragma unroll
        for (int s = 0; s < 4; s++) {
            const int q  = (s << 8) + tid;
            const int r  = q >> 3;
            const int c4 = (q & 7) << 2;
            const int ks = c4 >> 3;
            // ---- A: mf = r>>4, rr = r&15; reg = (rr>=8) + 2*(cc>=4)
            {
                const int mf = r >> 4, rr = r & 15;
                const int regb = ((rr >> 3) & 1) + (((c4 >> 2) & 1) << 1);
                uint32_t* base = As + (buf << 12) + ((ks * 8 + mf) << 7);
                const float v[4] = {pa[s].x, pa[s].y, pa[s].z, pa[s].w};
                #pragma unroll
                for (int j = 0; j < 4; j++) {
                    const int ln = ((rr & 7) << 2) + j;
                    base[((ln ^ ks) << 2) + regb] = f2tf(v[j]);
                }
            }
            // ---- B: nf = r>>3, nn = r&7; reg = (kk>=4)
            {
                const int nf = r >> 3, nn = r & 7;
                const int reg = (c4 >> 2) & 1;
                uint32_t* base = Bs + (buf << 12) + ((ks * 16 + nf) << 6);
                const float v[4] = {pb[s].x, pb[s].y, pb[s].z, pb[s].w};
                #pragma unroll
                for (int j = 0; j < 4; j++) {
                    const int ln = (nn << 2) + j;
                    base[((ln ^ ks) << 1) + reg] = f2tf(v[j]);
                }
            }
        }
    };

    auto compute = [&](int buf) {
        #pragma unroll
        for (int ks = 0; ks < 4; ks++) {
            uint32_t a[4][4], bfr[4][2];
            const int lx = lane ^ ks;
            #pragma unroll
            for (int mf = 0; mf < 4; mf++) {
                const uint32_t* p = As + (buf << 12)
                    + ((ks * 8 + wm * 4 + mf) << 7) + (lx << 2);
                uint4 t = *(const uint4*)p;
                a[mf][0] = t.x; a[mf][1] = t.y; a[mf][2] = t.z; a[mf][3] = t.w;
            }
            #pragma unroll
            for (int nf = 0; nf < 4; nf++) {
                const uint32_t* p = Bs + (buf << 12)
                    + ((ks * 16 + wn * 4 + nf) << 6) + (lx << 1);
                uint2 t = *(const uint2*)p;
                bfr[nf][0] = t.x; bfr[nf][1] = t.y;
            }
            #pragma unroll
            for (int mf = 0; mf < 4; mf++)
                #pragma unroll
                for (int nf = 0; nf < 4; nf++)
                    asm volatile(
                        "mma.sync.aligned.m16n8k8.row.col.f32.tf32.tf32.f32 "
                        "{%0,%1,%2,%3}, {%4,%5,%6,%7}, {%8,%9}, {%0,%1,%2,%3};"
                        : "+f"(acc[mf][nf][0]), "+f"(acc[mf][nf][1]),
                          "+f"(acc[mf][nf][2]), "+f"(acc[mf][nf][3])
                        : "r"(a[mf][0]), "r"(a[mf][1]), "r"(a[mf][2]), "r"(a[mf][3]),
                          "r"(bfr[nf][0]), "r"(bfr[nf][1]));
        }
    };

    loadg(0);
    stores(0);
    __syncthreads();

    for (int t = 0; t < 32; t++) {
        const int buf = t & 1;
        if (t + 1 < 32) loadg(t + 1);      // LDGs issue early, land in regs
        compute(buf);                       // hides gmem latency
        if (t + 1 < 32) stores(buf ^ 1);
        __syncthreads();
    }

    // ---- epilogue: acc regs -> C (+bias) ------------------------------------
    const int cbase = n0 + (wn << 5);
    float2 bv[4];
    #pragma unroll
    for (int nf = 0; nf < 4; nf++)
        bv[nf] = *(const float2*)(bias + cbase + (nf << 3) + ((lane & 3) << 1));

    #pragma unroll
    for (int mf = 0; mf < 4; mf++) {
        const long long rb =
            (long long)(m0 + (wm << 6) + (mf << 4) + (lane >> 2)) * DD + cbase;
        #pragma unroll
        for (int nf = 0; nf < 4; nf++) {
            const int co = (nf << 3) + ((lane & 3) << 1);
            float2 v0 = {acc[mf][nf][0] + bv[nf].x, acc[mf][nf][1] + bv[nf].y};
            float2 v1 = {acc[mf][nf][2] + bv[nf].x, acc[mf][nf][3] + bv[nf].y};
            *(float2*)(C + rb + co)           = v0;
            *(float2*)(C + rb + 8LL * DD + co) = v1;
        }
    }
}

// ---------------------------------------------------------------------------
// 1024x1024 transpose (Wq, Wv -> K-major B operands)
// ---------------------------------------------------------------------------
__global__ void __launch_bounds__(256) transpose_w(const float* __restrict__ W,
                                                   float* __restrict__ Wt)
{
    __shared__ float s[32][33];
    const int bx = blockIdx.x << 5, by = blockIdx.y << 5;
    const int tx = threadIdx.x & 31, ty = threadIdx.x >> 5;
    #pragma unroll
    for (int j = 0; j < 32; j += 8)
        s[ty + j][tx] = W[(size_t)(by + ty + j) * DD + bx + tx];
    __syncthreads();
    #pragma unroll
    for (int j = 0; j < 32; j += 8)
        Wt[(size_t)(bx + ty + j) * DD + by + tx] = s[tx][ty + j];
}

// ---------------------------------------------------------------------------
// Row softmax over d_head=64, in place on g_Q, times SCALE.
// ---------------------------------------------------------------------------
__global__ void __launch_bounds__(256) row_softmax()
{
    const size_t row = (size_t)blockIdx.x * 8 + (threadIdx.x >> 5);
    const int lane = threadIdx.x & 31;
    float* p = g_Q + row * DH + lane * 2;
    float2 v = *(float2*)p;
    float m = fmaxf(v.x, v.y);
    #pragma unroll
    for (int o = 16; o; o >>= 1) m = fmaxf(m, __shfl_xor_sync(0xffffffffu, m, o));
    float e0 = __expf(v.x - m), e1 = __expf(v.y - m);
    float s = e0 + e1;
    #pragma unroll
    for (int o = 16; o; o >>= 1) s += __shfl_xor_sync(0xffffffffu, s, o);
    float inv = SCALE / s;
    float2 o2 = {e0 * inv, e1 * inv};
    *(float2*)p = o2;
}

// ---------------------------------------------------------------------------
// Column softmax over seq dim N per (b, column).
// ---------------------------------------------------------------------------
__global__ void __launch_bounds__(512) col_softmax()
{
    const int b  = blockIdx.y;
    const int cl = threadIdx.x & 31;
    const int c  = (blockIdx.x << 5) + cl;
    const int r  = threadIdx.x >> 5;
    const float* src = g_Q  + (size_t)b * NN * DD + c;
    float*       dst = g_Km + (size_t)b * NN * DD + c;

    __shared__ float red[16][32];

    float m = -1e30f;
    for (int n = r; n < NN; n += 16) m = fmaxf(m, src[(size_t)n * DD]);
    red[r][cl] = m;
    __syncthreads();
    m = red[0][cl];
    #pragma unroll
    for (int i = 1; i < 16; i++) m = fmaxf(m, red[i][cl]);
    __syncthreads();

    float s = 0.f;
    for (int n = r; n < NN; n += 16) s += __expf(src[(size_t)n * DD] - m);
    red[r][cl] = s;
    __syncthreads();
    s = 0.f;
    #pragma unroll
    for (int i = 0; i < 16; i++) s += red[i][cl];

    const float inv = SCALE / s;
    for (int n = r; n < NN; n += 16)
        dst[(size_t)n * DD] = __expf(src[(size_t)n * DD] - m) * inv;
}

// ---------------------------------------------------------------------------
// ctx partials: g_ctx[sp][bh][d][e] = sum over n-slice of Km[n,d]*V[n,e].
// ---------------------------------------------------------------------------
__global__ void __launch_bounds__(256) ctx_kernel()
{
    const int bh = blockIdx.x, b = bh >> 4, h = bh & 15;
    const int n0 = blockIdx.y * (NN / NSPLIT);
    const float* Kp = g_Km + (size_t)b * NN * DD + h * DH;
    const float* Vp = g_V  + (size_t)b * NN * DD + h * DH;

    __shared__ float Ks[8][64], Vs[8][64];
    const int tid = threadIdx.x;
    const int lr = tid >> 5, lc = (tid & 31) << 1;
    const int rd = (tid >> 4) << 2, ce = (tid & 15) << 2;

    float acc[4][4] = {};
    for (int nk = 0; nk < NN / NSPLIT; nk += 8) {
        const size_t off = (size_t)(n0 + nk + lr) * DD + lc;
        *(float2*)&Ks[lr][lc] = *(const float2*)(Kp + off);
        *(float2*)&Vs[lr][lc] = *(const float2*)(Vp + off);
        __syncthreads();
        #pragma unroll
        for (int k = 0; k < 8; k++) {
            float a[4], v[4];
            *(float4*)a = *(float4*)&Ks[k][rd];
            *(float4*)v = *(float4*)&Vs[k][ce];
            #pragma unroll
            for (int i = 0; i < 4; i++)
                #pragma unroll
                for (int j = 0; j < 4; j++)
                    acc[i][j] = fmaf(a[i], v[j], acc[i][j]);
        }
        __syncthreads();
    }
    float* o = g_ctx + (((size_t)blockIdx.y * (BB * HH) + bh) << 12);
    #pragma unroll
    for (int i = 0; i < 4; i++) {
        float4 t = {acc[i][0], acc[i][1], acc[i][2], acc[i][3]};
        *(float4*)(o + (rd + i) * 64 + ce) = t;
    }
}

// ---------------------------------------------------------------------------
// Mbig^T[b][c][h*64+d] = sum_e ctx[b,h][d][e] * Wo[h*64+e][c]
// (K-major rows -> B operand of the final GEMM)
// ---------------------------------------------------------------------------
__global__ void __launch_bounds__(256) mbig_kernel(const float* __restrict__ Wo)
{
    const int bh = blockIdx.x, b = bh >> 4, h = bh & 15;
    const int c0 = blockIdx.y << 6;

    __shared__ float cs[64][64];
    __shared__ float ws[64][64];
    const int tid = threadIdx.x;

    for (int i = tid; i < 4096; i += 256) {
        float sum = 0.f;
        #pragma unroll
        for (int sp = 0; sp < NSPLIT; sp++)
            sum += g_ctx[(((size_t)sp * (BB * HH) + bh) << 12) + i];
        cs[i >> 6][i & 63] = sum;
    }
    for (int i = tid; i < 1024; i += 256) {
        int rr = i >> 4, cc = (i & 15) << 2;
        *(float4*)&ws[rr][cc] =
            *(const float4*)(Wo + (size_t)(h * DH + rr) * DD + c0 + cc);
    }
    __syncthreads();

    const int r0 = (tid >> 4) << 2, cc0 = (tid & 15) << 2;
    float acc[4][4] = {};
    #pragma unroll 16
    for (int k = 0; k < 64; k++) {
        float a[4], w[4];
        #pragma unroll
        for (int i = 0; i < 4; i++) a[i] = cs[r0 + i][k];
        *(float4*)w = *(float4*)&ws[k][cc0];
        #pragma unroll
        for (int i = 0; i < 4; i++)
            #pragma unroll
            for (int j = 0; j < 4; j++)
                acc[i][j] = fmaf(a[i], w[j], acc[i][j]);
    }
    float* out = g_Mt + ((size_t)b << 20);
    #pragma unroll
    for (int i = 0; i < 4; i++)
        #pragma unroll
        for (int j = 0; j < 4; j++)
            out[(size_t)(c0 + cc0 + j) * DD + h * DH + r0 + i] = acc[i][j];
}

// ---------------------------------------------------------------------------
// Launcher. Inputs: 0:x 1:Wq 2:bq 3:Wk(dead) 4:bk(dead) 5:Wv 6:bv 7:Wo 8:bo
// ---------------------------------------------------------------------------
extern "C" void kernel_launch(void* const* d_in, const int* in_sizes, int n_in,
                              void* d_out, int out_size)
{
    const float* x  = (const float*)d_in[0];
    const float* Wq = (const float*)d_in[1];
    const float* bq = (const float*)d_in[2];
    const float* Wv = (const float*)d_in[5];
    const float* bv = (const float*)d_in[6];
    const float* Wo = (const float*)d_in[7];
    const float* bo = (const float*)d_in[8];
    float* out = (float*)d_out;

    float *Q, *V, *Mt, *WqT, *WvT;
    cudaGetSymbolAddress((void**)&Q,   g_Q);
    cudaGetSymbolAddress((void**)&V,   g_V);
    cudaGetSymbolAddress((void**)&Mt,  g_Mt);
    cudaGetSymbolAddress((void**)&WqT, g_WqT);
    cudaGetSymbolAddress((void**)&WvT, g_WvT);

    cudaFuncSetAttribute((const void*)gemm_mma,
                         cudaFuncAttributeMaxDynamicSharedMemorySize, GEMM_SMEM);

    const long long sXD = (long long)NN * DD;
    dim3 ggrid(DD / 128, NN / 128, BB);
    dim3 tgrid(32, 32);

    // Weight transposes (K-major B operands)
    transpose_w<<<tgrid, 256>>>(Wq, WqT);
    transpose_w<<<tgrid, 256>>>(Wv, WvT);

    // Q = x@Wq + bq ; V = x@Wv + bv   (x@Wk is dead code in the reference)
    gemm_mma<<<ggrid, 256, GEMM_SMEM>>>(x, WqT, bq, Q, sXD, 0, sXD);
    gemm_mma<<<ggrid, 256, GEMM_SMEM>>>(x, WvT, bv, V, sXD, 0, sXD);

    // softmaxes
    row_softmax<<<(BB * NN * HH) / 8, 256>>>();
    col_softmax<<<dim3(DD / 32, BB), 512>>>();

    // ctx partials, then Mbig^T = (ctx @ Wo)^T per head
    ctx_kernel<<<dim3(BB * HH, NSPLIT), 256>>>();
    mbig_kernel<<<dim3(BB * HH, DD / 64), 256>>>(Wo);

    // out[b] = Qs[b] @ Mbig[b] + bo
    gemm_mma<<<ggrid, 256, GEMM_SMEM>>>(Q, Mt, bo, out,
                                        sXD, (long long)DD * DD, sXD);
}

// round 6
// speedup vs baseline: 3.8372x; 1.4165x over previous
#include <cuda_runtime.h>
#include <cstdint>

// Shapes fixed: B=4, N=4096, D=1024, H=16, d_head=64.
#define BB 4
#define NN 4096
#define DD 1024
#define DW 512            // packed bf16x2 words per row of 1024
#define HH 16
#define DH 64
#define NSPLIT 8
#define SCALE 0.5946035575013605f   // (d_head^0.5)^(-0.25) = 2^(-0.75)

// Scratch (__device__ globals; no cudaMalloc allowed).
__device__ float    g_Q  [(size_t)BB * NN * DD];   // Q proj -> row-softmaxed (in place)
__device__ float    g_V  [(size_t)BB * NN * DD];   // V proj
__device__ float    g_Km [(size_t)BB * NN * DD];   // column-softmax of Qs
__device__ float    g_ctx[(size_t)NSPLIT * BB * HH * DH * DH];
__device__ uint32_t g_xb [(size_t)BB * NN * DW];   // x packed bf16
__device__ uint32_t g_Qb [(size_t)BB * NN * DW];   // softmaxed Q packed bf16
__device__ uint32_t g_Wqb[(size_t)DD * DW];        // Wq^T packed bf16 (n-major, k contiguous)
__device__ uint32_t g_Wvb[(size_t)DD * DW];        // Wv^T packed bf16
__device__ uint32_t g_Mtb[(size_t)BB * DD * DW];   // Mbig^T packed bf16

// ---------------------------------------------------------------------------
// helpers
// ---------------------------------------------------------------------------
__device__ __forceinline__ uint32_t smem_u32(const void* p) {
    uint32_t a;
    asm("{ .reg .u64 t; cvta.to.shared.u64 t, %1; cvt.u32.u64 %0, t; }" : "=r"(a) : "l"(p));
    return a;
}
// pack2(lo, hi): lo -> lower bf16 (even k), hi -> upper (odd k)
__device__ __forceinline__ uint32_t pack2(float lo, float hi) {
    uint32_t r;
    asm("cvt.rn.bf16x2.f32 %0, %1, %2;" : "=r"(r) : "f"(hi), "f"(lo));
    return r;
}

// ---------------------------------------------------------------------------
// bf16 mma.sync GEMM: C[b] = A[b] @ Bt[b]^T + bias  (fp32 out)
//   A  packed bf16 rows [M][DW],  Bt packed bf16 rows [1024][DW] (row n, k contig)
// CTA 128x128, K-chunk 32 bf16 (2 x k16). 8 warps 2(m) x 4(n), warp tile 64x32.
// SMEM: canonical row-major, 64B rows (4 x 16B chunks), phys chunk = c ^ ((r>>1)&3).
// Loader: pure LDG.128 + STS.128. Compute: ldmatrix.x4 + mma m16n8k16 bf16.
// ---------------------------------------------------------------------------
__global__ void __launch_bounds__(256)
gemm_bf16(const uint32_t* __restrict__ A, const uint32_t* __restrict__ Bt,
          const float* __restrict__ bias, float* __restrict__ C,
          long long sA, long long sB, long long sC)
{
    __shared__ uint32_t sm[8192];   // A[2][2048] | B[2][2048]  = 32KB

    const int b = blockIdx.z;
    A  += (long long)b * sA;
    Bt += (long long)b * sB;
    C  += (long long)b * sC;
    const int n0 = blockIdx.x << 7;
    const int m0 = blockIdx.y << 7;
    const int tid = threadIdx.x, lane = tid & 31, wid = tid >> 5;
    const int wm = wid >> 2, wn = wid & 3;

    const uint32_t sbase = smem_u32(sm);

    // ---- loader coords: thread -> (row lr, 16-bf16 half lk8) ---------------
    const int lr  = tid >> 1;              // 0..127
    const int lk8 = (tid & 1) << 3;        // u32 offset 0 / 8
    const uint32_t* Ap = A  + (long long)(m0 + lr) * DW + lk8;
    const uint32_t* Bp = Bt + (long long)(n0 + lr) * DW + lk8;
    const int lswz = (lr >> 1) & 3;
    const int cb   = lk8 >> 2;             // chunk 0 or 2
    const uint32_t stA0 = sbase + (lr << 6) + ((cb ^ lswz) << 4);
    const uint32_t stA1 = sbase + (lr << 6) + (((cb + 1) ^ lswz) << 4);
    const uint32_t stB0 = stA0 + 16384;
    const uint32_t stB1 = stA1 + 16384;

    uint4 pa0, pa1, pb0, pb1;
    auto loadg = [&](int t) {
        const uint32_t* a  = Ap + (t << 4);
        const uint32_t* bb = Bp + (t << 4);
        pa0 = *(const uint4*)a;  pa1 = *(const uint4*)(a + 4);
        pb0 = *(const uint4*)bb; pb1 = *(const uint4*)(bb + 4);
    };
    auto stores = [&](int buf) {
        const uint32_t bo = (uint32_t)buf << 13;
        asm volatile("st.shared.v4.b32 [%0], {%1,%2,%3,%4};" :: "r"(stA0 + bo),
                     "r"(pa0.x), "r"(pa0.y), "r"(pa0.z), "r"(pa0.w) : "memory");
        asm volatile("st.shared.v4.b32 [%0], {%1,%2,%3,%4};" :: "r"(stA1 + bo),
                     "r"(pa1.x), "r"(pa1.y), "r"(pa1.z), "r"(pa1.w) : "memory");
        asm volatile("st.shared.v4.b32 [%0], {%1,%2,%3,%4};" :: "r"(stB0 + bo),
                     "r"(pb0.x), "r"(pb0.y), "r"(pb0.z), "r"(pb0.w) : "memory");
        asm volatile("st.shared.v4.b32 [%0], {%1,%2,%3,%4};" :: "r"(stB1 + bo),
                     "r"(pb1.x), "r"(pb1.y), "r"(pb1.z), "r"(pb1.w) : "memory");
    };

    // ---- per-lane ldmatrix geometry ----------------------------------------
    const int ar16 = lane & 15;                      // A row-in-16
    const int acs  = lane >> 4;                      // A k-half select
    const int aswz = (ar16 >> 1) & 3;
    const int br16 = (lane & 7) | ((lane & 16) >> 1);// B row-in-16
    const int bcs  = (lane >> 3) & 1;                // B k-half select
    const int bswz = (br16 >> 1) & 3;

    float acc[4][4][4];
    #pragma unroll
    for (int i = 0; i < 4; i++)
        #pragma unroll
        for (int j = 0; j < 4; j++)
            #pragma unroll
            for (int r = 0; r < 4; r++) acc[i][j][r] = 0.f;

    auto compute = [&](int buf) {
        const uint32_t abase = sbase + ((uint32_t)buf << 13) + (((wm << 6) + ar16) << 6);
        const uint32_t bbase = sbase + 16384u + ((uint32_t)buf << 13) + (((wn << 5) + br16) << 6);
        #pragma unroll
        for (int ks = 0; ks < 2; ks++) {
            uint32_t af[4][4], bg[2][4];
            const uint32_t ac = (uint32_t)((((ks << 1) + acs) ^ aswz) << 4);
            const uint32_t bc = (uint32_t)((((ks << 1) + bcs) ^ bswz) << 4);
            #pragma unroll
            for (int mf = 0; mf < 4; mf++)
                asm volatile("ldmatrix.sync.aligned.m8n8.x4.shared.b16 {%0,%1,%2,%3}, [%4];"
                    : "=r"(af[mf][0]), "=r"(af[mf][1]), "=r"(af[mf][2]), "=r"(af[mf][3])
                    : "r"(abase + (uint32_t)(mf << 10) + ac));
            #pragma unroll
            for (int np = 0; np < 2; np++)
                asm volatile("ldmatrix.sync.aligned.m8n8.x4.shared.b16 {%0,%1,%2,%3}, [%4];"
                    : "=r"(bg[np][0]), "=r"(bg[np][1]), "=r"(bg[np][2]), "=r"(bg[np][3])
                    : "r"(bbase + (uint32_t)(np << 10) + bc));
            #pragma unroll
            for (int mf = 0; mf < 4; mf++)
                #pragma unroll
                for (int nf = 0; nf < 4; nf++)
                    asm volatile(
                        "mma.sync.aligned.m16n8k16.row.col.f32.bf16.bf16.f32 "
                        "{%0,%1,%2,%3}, {%4,%5,%6,%7}, {%8,%9}, {%0,%1,%2,%3};"
                        : "+f"(acc[mf][nf][0]), "+f"(acc[mf][nf][1]),
                          "+f"(acc[mf][nf][2]), "+f"(acc[mf][nf][3])
                        : "r"(af[mf][0]), "r"(af[mf][1]), "r"(af[mf][2]), "r"(af[mf][3]),
                          "r"(bg[nf >> 1][(nf & 1) << 1]), "r"(bg[nf >> 1][((nf & 1) << 1) + 1]));
        }
    };

    loadg(0); stores(0); __syncthreads();
    for (int t = 0; t < 32; t++) {
        const int buf = t & 1;
        if (t + 1 < 32) loadg(t + 1);
        compute(buf);
        if (t + 1 < 32) stores(buf ^ 1);
        __syncthreads();
    }

    // ---- epilogue ----------------------------------------------------------
    const int cbase = n0 + (wn << 5);
    float2 bv[4];
    #pragma unroll
    for (int nf = 0; nf < 4; nf++)
        bv[nf] = *(const float2*)(bias + cbase + (nf << 3) + ((lane & 3) << 1));

    #pragma unroll
    for (int mf = 0; mf < 4; mf++) {
        const long long rb =
            (long long)(m0 + (wm << 6) + (mf << 4) + (lane >> 2)) * DD + cbase;
        #pragma unroll
        for (int nf = 0; nf < 4; nf++) {
            const int co = (nf << 3) + ((lane & 3) << 1);
            float2 v0 = {acc[mf][nf][0] + bv[nf].x, acc[mf][nf][1] + bv[nf].y};
            float2 v1 = {acc[mf][nf][2] + bv[nf].x, acc[mf][nf][3] + bv[nf].y};
            *(float2*)(C + rb + co)            = v0;
            *(float2*)(C + rb + 8LL * DD + co) = v1;
        }
    }
}

// ---------------------------------------------------------------------------
// pack_w: W[k][n] -> Wtb[n][k/2] packed bf16 pairs (transpose + pack)
// tile 64k x 32n, grid (1024/32, 1024/64)
// NOTE: row pad 36 floats (144B) keeps float4 accesses 16B-aligned
// (pad 33 caused the R5 "misaligned address" crash).
// ---------------------------------------------------------------------------
__global__ void __launch_bounds__(256) pack_w(const float* __restrict__ W,
                                              uint32_t* __restrict__ Wtb)
{
    __shared__ float s[64][36];
    const int n0 = blockIdx.x << 5, k0 = blockIdx.y << 6;
    const int tid = threadIdx.x;
    {
        const int i = tid >> 2, j8 = (tid & 3) << 3;
        *(float4*)&s[i][j8]     = *(const float4*)(W + (size_t)(k0 + i) * DD + n0 + j8);
        *(float4*)&s[i][j8 + 4] = *(const float4*)(W + (size_t)(k0 + i) * DD + n0 + j8 + 4);
    }
    __syncthreads();
    const int nl = tid >> 3, kg = tid & 7;
    uint4 o;
    o.x = pack2(s[kg * 8 + 0][nl], s[kg * 8 + 1][nl]);
    o.y = pack2(s[kg * 8 + 2][nl], s[kg * 8 + 3][nl]);
    o.z = pack2(s[kg * 8 + 4][nl], s[kg * 8 + 5][nl]);
    o.w = pack2(s[kg * 8 + 6][nl], s[kg * 8 + 7][nl]);
    *(uint4*)(Wtb + (size_t)(n0 + nl) * DW + (k0 >> 1) + (kg << 2)) = o;
}

// ---------------------------------------------------------------------------
// pack_rows: fp32 row-major -> packed bf16 (same layout)
// ---------------------------------------------------------------------------
__global__ void __launch_bounds__(256) pack_rows(const float* __restrict__ src,
                                                 uint32_t* __restrict__ dst)
{
    const size_t q = ((size_t)blockIdx.x * 256 + threadIdx.x) << 3;
    float4 a = *(const float4*)(src + q), b = *(const float4*)(src + q + 4);
    uint4 o = {pack2(a.x, a.y), pack2(a.z, a.w), pack2(b.x, b.y), pack2(b.z, b.w)};
    *(uint4*)(dst + (q >> 1)) = o;
}

// ---------------------------------------------------------------------------
// Row softmax over d_head=64, in place on g_Q (*SCALE), plus packed bf16 copy.
// ---------------------------------------------------------------------------
__global__ void __launch_bounds__(256) row_softmax()
{
    const size_t row = (size_t)blockIdx.x * 8 + (threadIdx.x >> 5);
    const int lane = threadIdx.x & 31;
    float* p = g_Q + row * DH + lane * 2;
    float2 v = *(float2*)p;
    float m = fmaxf(v.x, v.y);
    #pragma unroll
    for (int o = 16; o; o >>= 1) m = fmaxf(m, __shfl_xor_sync(0xffffffffu, m, o));
    float e0 = __expf(v.x - m), e1 = __expf(v.y - m);
    float s = e0 + e1;
    #pragma unroll
    for (int o = 16; o; o >>= 1) s += __shfl_xor_sync(0xffffffffu, s, o);
    float inv = SCALE / s;
    float2 o2 = {e0 * inv, e1 * inv};
    *(float2*)p = o2;
    g_Qb[(row >> 4) * DW + (row & 15) * 32 + lane] = pack2(o2.x, o2.y);
}

// ---------------------------------------------------------------------------
// Column softmax over seq dim N. 32 cols/CTA, float4 vectorized, coalesced.
// grid (DD/32, BB), block 512 = 8 col4-groups x 64 row-strides.
// ---------------------------------------------------------------------------
__global__ void __launch_bounds__(512) col_softmax()
{
    const int b  = blockIdx.y;
    const int c0 = blockIdx.x << 5;
    const int tx = threadIdx.x & 7;
    const int ty = threadIdx.x >> 3;
    const float* src = g_Q  + (size_t)b * NN * DD + c0 + (tx << 2);
    float*       dst = g_Km + (size_t)b * NN * DD + c0 + (tx << 2);

    __shared__ float4 red[64][8];

    float4 m4 = {-1e30f, -1e30f, -1e30f, -1e30f};
    for (int n = ty; n < NN; n += 64) {
        float4 v = *(const float4*)(src + (size_t)n * DD);
        m4.x = fmaxf(m4.x, v.x); m4.y = fmaxf(m4.y, v.y);
        m4.z = fmaxf(m4.z, v.z); m4.w = fmaxf(m4.w, v.w);
    }
    red[ty][tx] = m4;
    __syncthreads();
    m4 = red[0][tx];
    #pragma unroll 8
    for (int i = 1; i < 64; i++) {
        float4 r = red[i][tx];
        m4.x = fmaxf(m4.x, r.x); m4.y = fmaxf(m4.y, r.y);
        m4.z = fmaxf(m4.z, r.z); m4.w = fmaxf(m4.w, r.w);
    }
    __syncthreads();

    float4 s4 = {0.f, 0.f, 0.f, 0.f};
    for (int n = ty; n < NN; n += 64) {
        float4 v = *(const float4*)(src + (size_t)n * DD);
        s4.x += __expf(v.x - m4.x); s4.y += __expf(v.y - m4.y);
        s4.z += __expf(v.z - m4.z); s4.w += __expf(v.w - m4.w);
    }
    red[ty][tx] = s4;
    __syncthreads();
    s4.x = 0.f; s4.y = 0.f; s4.z = 0.f; s4.w = 0.f;
    #pragma unroll 8
    for (int i = 0; i < 64; i++) {
        float4 r = red[i][tx];
        s4.x += r.x; s4.y += r.y; s4.z += r.z; s4.w += r.w;
    }
    const float4 inv = {SCALE / s4.x, SCALE / s4.y, SCALE / s4.z, SCALE / s4.w};

    for (int n = ty; n < NN; n += 64) {
        float4 v = *(const float4*)(src + (size_t)n * DD);
        float4 o = {__expf(v.x - m4.x) * inv.x, __expf(v.y - m4.y) * inv.y,
                    __expf(v.z - m4.z) * inv.z, __expf(v.w - m4.w) * inv.w};
        *(float4*)(dst + (size_t)n * DD) = o;
    }
}

// ---------------------------------------------------------------------------
// ctx partials: g_ctx[sp][bh][d][e] = sum over n-slice of Km[n,d]*V[n,e].
// ---------------------------------------------------------------------------
__global__ void __launch_bounds__(256) ctx_kernel()
{
    const int bh = blockIdx.x, b = bh >> 4, h = bh & 15;
    const int n0 = blockIdx.y * (NN / NSPLIT);
    const float* Kp = g_Km + (size_t)b * NN * DD + h * DH;
    const float* Vp = g_V  + (size_t)b * NN * DD + h * DH;

    __shared__ float Ks[8][64], Vs[8][64];
    const int tid = threadIdx.x;
    const int lr = tid >> 5, lc = (tid & 31) << 1;
    const int rd = (tid >> 4) << 2, ce = (tid & 15) << 2;

    float acc[4][4] = {};
    for (int nk = 0; nk < NN / NSPLIT; nk += 8) {
        const size_t off = (size_t)(n0 + nk + lr) * DD + lc;
        *(float2*)&Ks[lr][lc] = *(const float2*)(Kp + off);
        *(float2*)&Vs[lr][lc] = *(const float2*)(Vp + off);
        __syncthreads();
        #pragma unroll
        for (int k = 0; k < 8; k++) {
            float a[4], v[4];
            *(float4*)a = *(float4*)&Ks[k][rd];
            *(float4*)v = *(float4*)&Vs[k][ce];
            #pragma unroll
            for (int i = 0; i < 4; i++)
                #pragma unroll
                for (int j = 0; j < 4; j++)
                    acc[i][j] = fmaf(a[i], v[j], acc[i][j]);
        }
        __syncthreads();
    }
    float* o = g_ctx + (((size_t)blockIdx.y * (BB * HH) + bh) << 12);
    #pragma unroll
    for (int i = 0; i < 4; i++) {
        float4 t = {acc[i][0], acc[i][1], acc[i][2], acc[i][3]};
        *(float4*)(o + (rd + i) * 64 + ce) = t;
    }
}

// ---------------------------------------------------------------------------
// Mbig^T packed: g_Mtb[b][n][k/2] = pack(sum_e ctx[b,h][d][e]*Wo[h*64+e][n])
// where k = h*64+d.  Grid (B*H, D/64), 256 threads.
// ---------------------------------------------------------------------------
__global__ void __launch_bounds__(256) mbig_kernel(const float* __restrict__ Wo)
{
    const int bh = blockIdx.x, b = bh >> 4, h = bh & 15;
    const int c0 = blockIdx.y << 6;

    __shared__ float cs[64][64];
    __shared__ float ws[64][64];
    const int tid = threadIdx.x;

    for (int i = tid; i < 4096; i += 256) {
        float sum = 0.f;
        #pragma unroll
        for (int sp = 0; sp < NSPLIT; sp++)
            sum += g_ctx[(((size_t)sp * (BB * HH) + bh) << 12) + i];
        cs[i >> 6][i & 63] = sum;
    }
    for (int i = tid; i < 1024; i += 256) {
        int rr = i >> 4, cc = (i & 15) << 2;
        *(float4*)&ws[rr][cc] =
            *(const float4*)(Wo + (size_t)(h * DH + rr) * DD + c0 + cc);
    }
    __syncthreads();

    const int r0 = (tid >> 4) << 2, cc0 = (tid & 15) << 2;
    float acc[4][4] = {};
    #pragma unroll 16
    for (int k = 0; k < 64; k++) {
        float a[4], w[4];
        #pragma unroll
        for (int i = 0; i < 4; i++) a[i] = cs[r0 + i][k];
        *(float4*)w = *(float4*)&ws[k][cc0];
        #pragma unroll
        for (int i = 0; i < 4; i++)
            #pragma unroll
            for (int j = 0; j < 4; j++)
                acc[i][j] = fmaf(a[i], w[j], acc[i][j]);
    }
    uint32_t* ob = g_Mtb + ((size_t)b * DD * DW);
    const int kb2 = (h * DH + r0) >> 1;        // k word index
    #pragma unroll
    for (int j = 0; j < 4; j++) {
        const size_t n = (size_t)(c0 + cc0 + j);
        ob[n * DW + kb2]     = pack2(acc[0][j], acc[1][j]);
        ob[n * DW + kb2 + 1] = pack2(acc[2][j], acc[3][j]);
    }
}

// ---------------------------------------------------------------------------
// Launcher. Inputs: 0:x 1:Wq 2:bq 3:Wk(dead) 4:bk(dead) 5:Wv 6:bv 7:Wo 8:bo
// ---------------------------------------------------------------------------
extern "C" void kernel_launch(void* const* d_in, const int* in_sizes, int n_in,
                              void* d_out, int out_size)
{
    const float* x  = (const float*)d_in[0];
    const float* Wq = (const float*)d_in[1];
    const float* bq = (const float*)d_in[2];
    const float* Wv = (const float*)d_in[5];
    const float* bv = (const float*)d_in[6];
    const float* Wo = (const float*)d_in[7];
    const float* bo = (const float*)d_in[8];
    float* out = (float*)d_out;

    float *Q, *V;
    uint32_t *xb, *Qb, *Wqb, *Wvb, *Mtb;
    cudaGetSymbolAddress((void**)&Q,   g_Q);
    cudaGetSymbolAddress((void**)&V,   g_V);
    cudaGetSymbolAddress((void**)&xb,  g_xb);
    cudaGetSymbolAddress((void**)&Qb,  g_Qb);
    cudaGetSymbolAddress((void**)&Wqb, g_Wqb);
    cudaGetSymbolAddress((void**)&Wvb, g_Wvb);
    cudaGetSymbolAddress((void**)&Mtb, g_Mtb);

    const long long sXW = (long long)NN * DW;   // packed row-block stride per batch
    const long long sXD = (long long)NN * DD;   // fp32 stride per batch
    dim3 ggrid(DD / 128, NN / 128, BB);

    // pack inputs to bf16
    pack_rows<<<(BB * NN * DD) / (256 * 8), 256>>>(x, xb);
    pack_w<<<dim3(DD / 32, DD / 64), 256>>>(Wq, Wqb);
    pack_w<<<dim3(DD / 32, DD / 64), 256>>>(Wv, Wvb);

    // Q = x@Wq + bq ; V = x@Wv + bv   (x@Wk is dead code in the reference)
    gemm_bf16<<<ggrid, 256>>>(xb, Wqb, bq, Q, sXW, 0, sXD);
    gemm_bf16<<<ggrid, 256>>>(xb, Wvb, bv, V, sXW, 0, sXD);

    // softmaxes (row_softmax also emits packed bf16 Qb)
    row_softmax<<<(BB * NN * HH) / 8, 256>>>();
    col_softmax<<<dim3(DD / 32, BB), 512>>>();

    // ctx partials, then Mbig^T packed
    ctx_kernel<<<dim3(BB * HH, NSPLIT), 256>>>();
    mbig_kernel<<<dim3(BB * HH, DD / 64), 256>>>(Wo);

    // out[b] = Qs[b] @ Mbig[b] + bo
    gemm_bf16<<<ggrid, 256>>>(Qb, Mtb, bo, out,
                              sXW, (long long)DD * DW, sXD);
}

// round 7
// speedup vs baseline: 5.0501x; 1.3161x over previous
#include <cuda_runtime.h>
#include <cstdint>

// Shapes fixed: B=4, N=4096, D=1024, H=16, d_head=64.
#define BB 4
#define NN 4096
#define DD 1024
#define DW 512            // packed bf16x2 words per row of 1024
#define HH 16
#define DH 64
#define NSPLIT 8
#define SCALE 0.5946035575013605f   // (d_head^0.5)^(-0.25) = 2^(-0.75)

// Scratch (__device__ globals; no cudaMalloc allowed).
__device__ float    g_Q  [(size_t)BB * NN * DD];   // Q proj -> row-softmaxed (in place)
__device__ float    g_V  [(size_t)BB * NN * DD];   // V proj
__device__ float    g_Km [(size_t)BB * NN * DD];   // column-softmax of Qs
__device__ float    g_ctx[(size_t)NSPLIT * BB * HH * DH * DH];
__device__ uint32_t g_xb [(size_t)BB * NN * DW];   // x packed bf16
__device__ uint32_t g_Qb [(size_t)BB * NN * DW];   // softmaxed Q packed bf16
__device__ uint32_t g_Wqb[(size_t)DD * DW];        // Wq^T packed bf16 (n-major, k contiguous)
__device__ uint32_t g_Wvb[(size_t)DD * DW];        // Wv^T packed bf16
__device__ uint32_t g_Mtb[(size_t)BB * DD * DW];   // Mbig^T packed bf16

// ---------------------------------------------------------------------------
// helpers
// ---------------------------------------------------------------------------
__device__ __forceinline__ uint32_t smem_u32(const void* p) {
    uint32_t a;
    asm("{ .reg .u64 t; cvta.to.shared.u64 t, %1; cvt.u32.u64 %0, t; }" : "=r"(a) : "l"(p));
    return a;
}
// pack2(lo, hi): lo -> lower bf16 (even k), hi -> upper (odd k)
__device__ __forceinline__ uint32_t pack2(float lo, float hi) {
    uint32_t r;
    asm("cvt.rn.bf16x2.f32 %0, %1, %2;" : "=r"(r) : "f"(hi), "f"(lo));
    return r;
}
#define CP_ASYNC16(dst, src) \
    asm volatile("cp.async.cg.shared.global [%0], [%1], 16;" :: "r"(dst), "l"(src) : "memory")
#define CP_COMMIT()  asm volatile("cp.async.commit_group;" ::: "memory")
#define CP_WAIT2()   asm volatile("cp.async.wait_group 2;" ::: "memory")

// ---------------------------------------------------------------------------
// bf16 mma.sync GEMM: C[b] = A[b] @ Bt[b]^T + bias  (fp32 out)
//   A  packed bf16 rows [M][DW],  Bt packed bf16 rows [1024][DW] (row n, k contig)
// CTA 128x128, K-chunk 32 bf16. 8 warps 2(m) x 4(n), warp tile 64x32.
// SMEM: 4-stage cp.async ring, 16KB/stage (A 8KB | B 8KB); canonical row-major
// 64B rows (4 x 16B chunks), phys chunk = c ^ ((r>>1)&3).
// Compute: ldmatrix.x4 + mma m16n8k16 bf16.  2 CTAs/SM (128-reg cap).
// ---------------------------------------------------------------------------
#define GEMM_SMEM 65536

__global__ void __launch_bounds__(256, 2)
gemm_bf16(const uint32_t* __restrict__ A, const uint32_t* __restrict__ Bt,
          const float* __restrict__ bias, float* __restrict__ C,
          long long sA, long long sB, long long sC)
{
    extern __shared__ uint32_t sm[];

    const int b = blockIdx.z;
    A  += (long long)b * sA;
    Bt += (long long)b * sB;
    C  += (long long)b * sC;
    const int n0 = blockIdx.x << 7;
    const int m0 = blockIdx.y << 7;
    const int tid = threadIdx.x, lane = tid & 31, wid = tid >> 5;
    const int wm = wid >> 2, wn = wid & 3;

    const uint32_t sbase = smem_u32(sm);

    // ---- async loader coords: thread -> (row lr, 32B half lk8) -------------
    const int lr  = tid >> 1;              // 0..127
    const int lk8 = (tid & 1) << 3;        // u32 offset 0 / 8
    const uint32_t* Ap = A  + (long long)(m0 + lr) * DW + lk8;
    const uint32_t* Bp = Bt + (long long)(n0 + lr) * DW + lk8;
    const int lswz = (lr >> 1) & 3;
    const int cb   = lk8 >> 2;             // chunk 0 or 2
    const uint32_t stA0 = sbase + (lr << 6) + ((cb ^ lswz) << 4);
    const uint32_t stA1 = sbase + (lr << 6) + (((cb + 1) ^ lswz) << 4);

    auto issue = [&](int t) {              // stage (t & 3) <- K-chunk t
        const uint32_t so = (uint32_t)(t & 3) << 14;
        const uint32_t* a  = Ap + (t << 4);
        const uint32_t* bb = Bp + (t << 4);
        CP_ASYNC16(stA0 + so,         a);
        CP_ASYNC16(stA1 + so,         a + 4);
        CP_ASYNC16(stA0 + so + 8192u, bb);
        CP_ASYNC16(stA1 + so + 8192u, bb + 4);
    };

    // ---- per-lane ldmatrix geometry ----------------------------------------
    const int ar16 = lane & 15;                      // A row-in-16
    const int acs  = lane >> 4;                      // A k-half select
    const int aswz = (ar16 >> 1) & 3;
    const int br16 = (lane & 7) | ((lane & 16) >> 1);// B row-in-16
    const int bcs  = (lane >> 3) & 1;                // B k-half select
    const int bswz = (br16 >> 1) & 3;

    float acc[4][4][4];
    #pragma unroll
    for (int i = 0; i < 4; i++)
        #pragma unroll
        for (int j = 0; j < 4; j++)
            #pragma unroll
            for (int r = 0; r < 4; r++) acc[i][j][r] = 0.f;

    auto compute = [&](int stg) {
        const uint32_t so = (uint32_t)stg << 14;
        const uint32_t abase = sbase + so + (((wm << 6) + ar16) << 6);
        const uint32_t bbase = sbase + so + 8192u + (((wn << 5) + br16) << 6);
        #pragma unroll
        for (int ks = 0; ks < 2; ks++) {
            uint32_t af[4][4], bg[2][4];
            const uint32_t ac = (uint32_t)((((ks << 1) + acs) ^ aswz) << 4);
            const uint32_t bc = (uint32_t)((((ks << 1) + bcs) ^ bswz) << 4);
            #pragma unroll
            for (int mf = 0; mf < 4; mf++)
                asm volatile("ldmatrix.sync.aligned.m8n8.x4.shared.b16 {%0,%1,%2,%3}, [%4];"
                    : "=r"(af[mf][0]), "=r"(af[mf][1]), "=r"(af[mf][2]), "=r"(af[mf][3])
                    : "r"(abase + (uint32_t)(mf << 10) + ac));
            #pragma unroll
            for (int np = 0; np < 2; np++)
                asm volatile("ldmatrix.sync.aligned.m8n8.x4.shared.b16 {%0,%1,%2,%3}, [%4];"
                    : "=r"(bg[np][0]), "=r"(bg[np][1]), "=r"(bg[np][2]), "=r"(bg[np][3])
                    : "r"(bbase + (uint32_t)(np << 10) + bc));
            #pragma unroll
            for (int mf = 0; mf < 4; mf++)
                #pragma unroll
                for (int nf = 0; nf < 4; nf++)
                    asm volatile(
                        "mma.sync.aligned.m16n8k16.row.col.f32.bf16.bf16.f32 "
                        "{%0,%1,%2,%3}, {%4,%5,%6,%7}, {%8,%9}, {%0,%1,%2,%3};"
                        : "+f"(acc[mf][nf][0]), "+f"(acc[mf][nf][1]),
                          "+f"(acc[mf][nf][2]), "+f"(acc[mf][nf][3])
                        : "r"(af[mf][0]), "r"(af[mf][1]), "r"(af[mf][2]), "r"(af[mf][3]),
                          "r"(bg[nf >> 1][(nf & 1) << 1]), "r"(bg[nf >> 1][((nf & 1) << 1) + 1]));
        }
    };

    // ---- 4-stage pipeline ---------------------------------------------------
    issue(0); CP_COMMIT();
    issue(1); CP_COMMIT();
    issue(2); CP_COMMIT();

    for (int t = 0; t < 32; t++) {
        CP_WAIT2();                 // group t (stage t) complete
        __syncthreads();            // all warps see stage t; buf (t&3) free for reuse
        compute(t & 3);
        if (t + 3 < 32) issue(t + 3);
        CP_COMMIT();                // one group per iteration keeps wait counts aligned
    }

    // ---- epilogue ----------------------------------------------------------
    const int cbase = n0 + (wn << 5);
    float2 bv[4];
    #pragma unroll
    for (int nf = 0; nf < 4; nf++)
        bv[nf] = *(const float2*)(bias + cbase + (nf << 3) + ((lane & 3) << 1));

    #pragma unroll
    for (int mf = 0; mf < 4; mf++) {
        const long long rb =
            (long long)(m0 + (wm << 6) + (mf << 4) + (lane >> 2)) * DD + cbase;
        #pragma unroll
        for (int nf = 0; nf < 4; nf++) {
            const int co = (nf << 3) + ((lane & 3) << 1);
            float2 v0 = {acc[mf][nf][0] + bv[nf].x, acc[mf][nf][1] + bv[nf].y};
            float2 v1 = {acc[mf][nf][2] + bv[nf].x, acc[mf][nf][3] + bv[nf].y};
            *(float2*)(C + rb + co)            = v0;
            *(float2*)(C + rb + 8LL * DD + co) = v1;
        }
    }
}

// ---------------------------------------------------------------------------
// pack_w: W[k][n] -> Wtb[n][k/2] packed bf16 pairs (transpose + pack)
// tile 64k x 32n, grid (1024/32, 1024/64). Row pad 36 keeps float4 16B-aligned.
// ---------------------------------------------------------------------------
__global__ void __launch_bounds__(256) pack_w(const float* __restrict__ W,
                                              uint32_t* __restrict__ Wtb)
{
    __shared__ float s[64][36];
    const int n0 = blockIdx.x << 5, k0 = blockIdx.y << 6;
    const int tid = threadIdx.x;
    {
        const int i = tid >> 2, j8 = (tid & 3) << 3;
        *(float4*)&s[i][j8]     = *(const float4*)(W + (size_t)(k0 + i) * DD + n0 + j8);
        *(float4*)&s[i][j8 + 4] = *(const float4*)(W + (size_t)(k0 + i) * DD + n0 + j8 + 4);
    }
    __syncthreads();
    const int nl = tid >> 3, kg = tid & 7;
    uint4 o;
    o.x = pack2(s[kg * 8 + 0][nl], s[kg * 8 + 1][nl]);
    o.y = pack2(s[kg * 8 + 2][nl], s[kg * 8 + 3][nl]);
    o.z = pack2(s[kg * 8 + 4][nl], s[kg * 8 + 5][nl]);
    o.w = pack2(s[kg * 8 + 6][nl], s[kg * 8 + 7][nl]);
    *(uint4*)(Wtb + (size_t)(n0 + nl) * DW + (k0 >> 1) + (kg << 2)) = o;
}

// ---------------------------------------------------------------------------
// pack_rows: fp32 row-major -> packed bf16 (same layout)
// ---------------------------------------------------------------------------
__global__ void __launch_bounds__(256) pack_rows(const float* __restrict__ src,
                                                 uint32_t* __restrict__ dst)
{
    const size_t q = ((size_t)blockIdx.x * 256 + threadIdx.x) << 3;
    float4 a = *(const float4*)(src + q), b = *(const float4*)(src + q + 4);
    uint4 o = {pack2(a.x, a.y), pack2(a.z, a.w), pack2(b.x, b.y), pack2(b.z, b.w)};
    *(uint4*)(dst + (q >> 1)) = o;
}

// ---------------------------------------------------------------------------
// Row softmax over d_head=64, in place on g_Q (*SCALE), plus packed bf16 copy.
// ---------------------------------------------------------------------------
__global__ void __launch_bounds__(256) row_softmax()
{
    const size_t row = (size_t)blockIdx.x * 8 + (threadIdx.x >> 5);
    const int lane = threadIdx.x & 31;
    float* p = g_Q + row * DH + lane * 2;
    float2 v = *(float2*)p;
    float m = fmaxf(v.x, v.y);
    #pragma unroll
    for (int o = 16; o; o >>= 1) m = fmaxf(m, __shfl_xor_sync(0xffffffffu, m, o));
    float e0 = __expf(v.x - m), e1 = __expf(v.y - m);
    float s = e0 + e1;
    #pragma unroll
    for (int o = 16; o; o >>= 1) s += __shfl_xor_sync(0xffffffffu, s, o);
    float inv = SCALE / s;
    float2 o2 = {e0 * inv, e1 * inv};
    *(float2*)p = o2;
    g_Qb[(row >> 4) * DW + (row & 15) * 32 + lane] = pack2(o2.x, o2.y);
}

// ---------------------------------------------------------------------------
// Column softmax over seq dim N. 32 cols/CTA, float4 vectorized, coalesced.
// ---------------------------------------------------------------------------
__global__ void __launch_bounds__(512) col_softmax()
{
    const int b  = blockIdx.y;
    const int c0 = blockIdx.x << 5;
    const int tx = threadIdx.x & 7;
    const int ty = threadIdx.x >> 3;
    const float* src = g_Q  + (size_t)b * NN * DD + c0 + (tx << 2);
    float*       dst = g_Km + (size_t)b * NN * DD + c0 + (tx << 2);

    __shared__ float4 red[64][8];

    float4 m4 = {-1e30f, -1e30f, -1e30f, -1e30f};
    for (int n = ty; n < NN; n += 64) {
        float4 v = *(const float4*)(src + (size_t)n * DD);
        m4.x = fmaxf(m4.x, v.x); m4.y = fmaxf(m4.y, v.y);
        m4.z = fmaxf(m4.z, v.z); m4.w = fmaxf(m4.w, v.w);
    }
    red[ty][tx] = m4;
    __syncthreads();
    m4 = red[0][tx];
    #pragma unroll 8
    for (int i = 1; i < 64; i++) {
        float4 r = red[i][tx];
        m4.x = fmaxf(m4.x, r.x); m4.y = fmaxf(m4.y, r.y);
        m4.z = fmaxf(m4.z, r.z); m4.w = fmaxf(m4.w, r.w);
    }
    __syncthreads();

    float4 s4 = {0.f, 0.f, 0.f, 0.f};
    for (int n = ty; n < NN; n += 64) {
        float4 v = *(const float4*)(src + (size_t)n * DD);
        s4.x += __expf(v.x - m4.x); s4.y += __expf(v.y - m4.y);
        s4.z += __expf(v.z - m4.z); s4.w += __expf(v.w - m4.w);
    }
    red[ty][tx] = s4;
    __syncthreads();
    s4.x = 0.f; s4.y = 0.f; s4.z = 0.f; s4.w = 0.f;
    #pragma unroll 8
    for (int i = 0; i < 64; i++) {
        float4 r = red[i][tx];
        s4.x += r.x; s4.y += r.y; s4.z += r.z; s4.w += r.w;
    }
    const float4 inv = {SCALE / s4.x, SCALE / s4.y, SCALE / s4.z, SCALE / s4.w};

    for (int n = ty; n < NN; n += 64) {
        float4 v = *(const float4*)(src + (size_t)n * DD);
        float4 o = {__expf(v.x - m4.x) * inv.x, __expf(v.y - m4.y) * inv.y,
                    __expf(v.z - m4.z) * inv.z, __expf(v.w - m4.w) * inv.w};
        *(float4*)(dst + (size_t)n * DD) = o;
    }
}

// ---------------------------------------------------------------------------
// ctx partials: g_ctx[sp][bh][d][e] = sum over n-slice of Km[n,d]*V[n,e].
// ---------------------------------------------------------------------------
__global__ void __launch_bounds__(256) ctx_kernel()
{
    const int bh = blockIdx.x, b = bh >> 4, h = bh & 15;
    const int n0 = blockIdx.y * (NN / NSPLIT);
    const float* Kp = g_Km + (size_t)b * NN * DD + h * DH;
    const float* Vp = g_V  + (size_t)b * NN * DD + h * DH;

    __shared__ float Ks[8][64], Vs[8][64];
    const int tid = threadIdx.x;
    const int lr = tid >> 5, lc = (tid & 31) << 1;
    const int rd = (tid >> 4) << 2, ce = (tid & 15) << 2;

    float acc[4][4] = {};
    for (int nk = 0; nk < NN / NSPLIT; nk += 8) {
        const size_t off = (size_t)(n0 + nk + lr) * DD + lc;
        *(float2*)&Ks[lr][lc] = *(const float2*)(Kp + off);
        *(float2*)&Vs[lr][lc] = *(const float2*)(Vp + off);
        __syncthreads();
        #pragma unroll
        for (int k = 0; k < 8; k++) {
            float a[4], v[4];
            *(float4*)a = *(float4*)&Ks[k][rd];
            *(float4*)v = *(float4*)&Vs[k][ce];
            #pragma unroll
            for (int i = 0; i < 4; i++)
                #pragma unroll
                for (int j = 0; j < 4; j++)
                    acc[i][j] = fmaf(a[i], v[j], acc[i][j]);
        }
        __syncthreads();
    }
    float* o = g_ctx + (((size_t)blockIdx.y * (BB * HH) + bh) << 12);
    #pragma unroll
    for (int i = 0; i < 4; i++) {
        float4 t = {acc[i][0], acc[i][1], acc[i][2], acc[i][3]};
        *(float4*)(o + (rd + i) * 64 + ce) = t;
    }
}

// ---------------------------------------------------------------------------
// Mbig^T packed: g_Mtb[b][n][k/2] = pack(sum_e ctx[b,h][d][e]*Wo[h*64+e][n])
// ---------------------------------------------------------------------------
__global__ void __launch_bounds__(256) mbig_kernel(const float* __restrict__ Wo)
{
    const int bh = blockIdx.x, b = bh >> 4, h = bh & 15;
    const int c0 = blockIdx.y << 6;

    __shared__ float cs[64][64];
    __shared__ float ws[64][64];
    const int tid = threadIdx.x;

    for (int i = tid; i < 4096; i += 256) {
        float sum = 0.f;
        #pragma unroll
        for (int sp = 0; sp < NSPLIT; sp++)
            sum += g_ctx[(((size_t)sp * (BB * HH) + bh) << 12) + i];
        cs[i >> 6][i & 63] = sum;
    }
    for (int i = tid; i < 1024; i += 256) {
        int rr = i >> 4, cc = (i & 15) << 2;
        *(float4*)&ws[rr][cc] =
            *(const float4*)(Wo + (size_t)(h * DH + rr) * DD + c0 + cc);
    }
    __syncthreads();

    const int r0 = (tid >> 4) << 2, cc0 = (tid & 15) << 2;
    float acc[4][4] = {};
    #pragma unroll 16
    for (int k = 0; k < 64; k++) {
        float a[4], w[4];
        #pragma unroll
        for (int i = 0; i < 4; i++) a[i] = cs[r0 + i][k];
        *(float4*)w = *(float4*)&ws[k][cc0];
        #pragma unroll
        for (int i = 0; i < 4; i++)
            #pragma unroll
            for (int j = 0; j < 4; j++)
                acc[i][j] = fmaf(a[i], w[j], acc[i][j]);
    }
    uint32_t* ob = g_Mtb + ((size_t)b * DD * DW);
    const int kb2 = (h * DH + r0) >> 1;        // k word index
    #pragma unroll
    for (int j = 0; j < 4; j++) {
        const size_t n = (size_t)(c0 + cc0 + j);
        ob[n * DW + kb2]     = pack2(acc[0][j], acc[1][j]);
        ob[n * DW + kb2 + 1] = pack2(acc[2][j], acc[3][j]);
    }
}

// ---------------------------------------------------------------------------
// Launcher. Inputs: 0:x 1:Wq 2:bq 3:Wk(dead) 4:bk(dead) 5:Wv 6:bv 7:Wo 8:bo
// ---------------------------------------------------------------------------
extern "C" void kernel_launch(void* const* d_in, const int* in_sizes, int n_in,
                              void* d_out, int out_size)
{
    const float* x  = (const float*)d_in[0];
    const float* Wq = (const float*)d_in[1];
    const float* bq = (const float*)d_in[2];
    const float* Wv = (const float*)d_in[5];
    const float* bv = (const float*)d_in[6];
    const float* Wo = (const float*)d_in[7];
    const float* bo = (const float*)d_in[8];
    float* out = (float*)d_out;

    float *Q, *V;
    uint32_t *xb, *Qb, *Wqb, *Wvb, *Mtb;
    cudaGetSymbolAddress((void**)&Q,   g_Q);
    cudaGetSymbolAddress((void**)&V,   g_V);
    cudaGetSymbolAddress((void**)&xb,  g_xb);
    cudaGetSymbolAddress((void**)&Qb,  g_Qb);
    cudaGetSymbolAddress((void**)&Wqb, g_Wqb);
    cudaGetSymbolAddress((void**)&Wvb, g_Wvb);
    cudaGetSymbolAddress((void**)&Mtb, g_Mtb);

    cudaFuncSetAttribute((const void*)gemm_bf16,
                         cudaFuncAttributeMaxDynamicSharedMemorySize, GEMM_SMEM);

    const long long sXW = (long long)NN * DW;   // packed stride per batch
    const long long sXD = (long long)NN * DD;   // fp32 stride per batch
    dim3 ggrid(DD / 128, NN / 128, BB);

    // pack inputs to bf16
    pack_rows<<<(BB * NN * DD) / (256 * 8), 256>>>(x, xb);
    pack_w<<<dim3(DD / 32, DD / 64), 256>>>(Wq, Wqb);
    pack_w<<<dim3(DD / 32, DD / 64), 256>>>(Wv, Wvb);

    // Q = x@Wq + bq ; V = x@Wv + bv   (x@Wk is dead code in the reference)
    gemm_bf16<<<ggrid, 256, GEMM_SMEM>>>(xb, Wqb, bq, Q, sXW, 0, sXD);
    gemm_bf16<<<ggrid, 256, GEMM_SMEM>>>(xb, Wvb, bv, V, sXW, 0, sXD);

    // softmaxes (row_softmax also emits packed bf16 Qb)
    row_softmax<<<(BB * NN * HH) / 8, 256>>>();
    col_softmax<<<dim3(DD / 32, BB), 512>>>();

    // ctx partials, then Mbig^T packed
    ctx_kernel<<<dim3(BB * HH, NSPLIT), 256>>>();
    mbig_kernel<<<dim3(BB * HH, DD / 64), 256>>>(Wo);

    // out[b] = Qs[b] @ Mbig[b] + bo
    gemm_bf16<<<ggrid, 256, GEMM_SMEM>>>(Qb, Mtb, bo, out,
                                         sXW, (long long)DD * DW, sXD);
}

// round 8
// speedup vs baseline: 6.1959x; 1.2269x over previous
#include <cuda_runtime.h>
#include <cstdint>

// Shapes fixed: B=4, N=4096, D=1024, H=16, d_head=64.
#define BB 4
#define NN 4096
#define DD 1024
#define DW 512            // packed bf16x2 words per row of 1024
#define HH 16
#define DH 64
#define CTXSP 2
#define SCALE 0.5946035575013605f   // (d_head^0.5)^(-0.25) = 2^(-0.75)

// Scratch (__device__ globals; no cudaMalloc allowed).
__device__ float    g_Q  [(size_t)BB * NN * DD];   // Q proj, row-softmaxed (fp32, for col_softmax)
__device__ float    g_ctx[(size_t)CTXSP * BB * HH * DH * DH];
__device__ uint32_t g_xb [(size_t)BB * NN * DW];   // x packed bf16
__device__ uint32_t g_Qb [(size_t)BB * NN * DW];   // softmaxed Q packed bf16
__device__ uint32_t g_Vb [(size_t)BB * NN * DW];   // V proj packed bf16
__device__ uint32_t g_KmB[(size_t)BB * NN * DW];   // column-softmax packed bf16
__device__ uint32_t g_Wqb[(size_t)DD * DW];        // Wq^T packed bf16
__device__ uint32_t g_Wvb[(size_t)DD * DW];        // Wv^T packed bf16
__device__ uint32_t g_Mtb[(size_t)BB * DD * DW];   // Mbig^T packed bf16

// ---------------------------------------------------------------------------
// helpers
// ---------------------------------------------------------------------------
__device__ __forceinline__ uint32_t smem_u32(const void* p) {
    uint32_t a;
    asm("{ .reg .u64 t; cvta.to.shared.u64 t, %1; cvt.u32.u64 %0, t; }" : "=r"(a) : "l"(p));
    return a;
}
__device__ __forceinline__ uint32_t pack2(float lo, float hi) {
    uint32_t r;
    asm("cvt.rn.bf16x2.f32 %0, %1, %2;" : "=r"(r) : "f"(hi), "f"(lo));
    return r;
}
#define CP_ASYNC16(dst, src) \
    asm volatile("cp.async.cg.shared.global [%0], [%1], 16;" :: "r"(dst), "l"(src) : "memory")
#define CP_COMMIT()  asm volatile("cp.async.commit_group;" ::: "memory")
#define CP_WAIT2()   asm volatile("cp.async.wait_group 2;" ::: "memory")

#define LDM_X4(r, a)                                                            \
    asm volatile("ldmatrix.sync.aligned.m8n8.x4.shared.b16 {%0,%1,%2,%3}, [%4];"\
        : "=r"((r)[0]), "=r"((r)[1]), "=r"((r)[2]), "=r"((r)[3]) : "r"(a))
#define LDM_X4T(r, a)                                                           \
    asm volatile("ldmatrix.sync.aligned.m8n8.x4.trans.shared.b16 {%0,%1,%2,%3}, [%4];"\
        : "=r"((r)[0]), "=r"((r)[1]), "=r"((r)[2]), "=r"((r)[3]) : "r"(a))
#define MMA_BF16(d, a, b0, b1)                                                  \
    asm volatile("mma.sync.aligned.m16n8k16.row.col.f32.bf16.bf16.f32 "         \
        "{%0,%1,%2,%3}, {%4,%5,%6,%7}, {%8,%9}, {%0,%1,%2,%3};"                 \
        : "+f"((d)[0]), "+f"((d)[1]), "+f"((d)[2]), "+f"((d)[3])                \
        : "r"((a)[0]), "r"((a)[1]), "r"((a)[2]), "r"((a)[3]), "r"(b0), "r"(b1))

// ---------------------------------------------------------------------------
// bf16 mma.sync GEMM.  MODE 0: C=fp32+bias.  MODE 1: row-softmax(+bias) over
// 64-col heads, writes fp32 C AND packed Cb.  MODE 2: bias, packed Cb only.
// CTA 128x128, K-chunk 32 bf16, 4-stage cp.async ring, 2 CTAs/SM.
// ---------------------------------------------------------------------------
#define GEMM_SMEM 65536

template <int MODE>
__global__ void __launch_bounds__(256, 2)
gemm_bf16(const uint32_t* __restrict__ A, const uint32_t* __restrict__ Bt,
          const float* __restrict__ bias, float* __restrict__ C,
          uint32_t* __restrict__ Cb,
          long long sA, long long sB, long long sC)
{
    extern __shared__ uint32_t sm[];

    const int b = blockIdx.z;
    A  += (long long)b * sA;
    Bt += (long long)b * sB;
    C  += (long long)b * sC;
    Cb += (long long)b * NN * DW;
    const int n0 = blockIdx.x << 7;
    const int m0 = blockIdx.y << 7;
    const int tid = threadIdx.x, lane = tid & 31, wid = tid >> 5;
    const int wm = wid >> 2, wn = wid & 3;

    const uint32_t sbase = smem_u32(sm);

    const int lr  = tid >> 1;
    const int lk8 = (tid & 1) << 3;
    const uint32_t* Ap = A  + (long long)(m0 + lr) * DW + lk8;
    const uint32_t* Bp = Bt + (long long)(n0 + lr) * DW + lk8;
    const int lswz = (lr >> 1) & 3;
    const int cb   = lk8 >> 2;
    const uint32_t stA0 = sbase + (lr << 6) + ((cb ^ lswz) << 4);
    const uint32_t stA1 = sbase + (lr << 6) + (((cb + 1) ^ lswz) << 4);

    auto issue = [&](int t) {
        const uint32_t so = (uint32_t)(t & 3) << 14;
        const uint32_t* a  = Ap + (t << 4);
        const uint32_t* bb = Bp + (t << 4);
        CP_ASYNC16(stA0 + so,         a);
        CP_ASYNC16(stA1 + so,         a + 4);
        CP_ASYNC16(stA0 + so + 8192u, bb);
        CP_ASYNC16(stA1 + so + 8192u, bb + 4);
    };

    const int ar16 = lane & 15;
    const int acs  = lane >> 4;
    const int aswz = (ar16 >> 1) & 3;
    const int br16 = (lane & 7) | ((lane & 16) >> 1);
    const int bcs  = (lane >> 3) & 1;
    const int bswz = (br16 >> 1) & 3;

    float acc[4][4][4];
    #pragma unroll
    for (int i = 0; i < 4; i++)
        #pragma unroll
        for (int j = 0; j < 4; j++)
            #pragma unroll
            for (int r = 0; r < 4; r++) acc[i][j][r] = 0.f;

    auto compute = [&](int stg) {
        const uint32_t so = (uint32_t)stg << 14;
        const uint32_t abase = sbase + so + (((wm << 6) + ar16) << 6);
        const uint32_t bbase = sbase + so + 8192u + (((wn << 5) + br16) << 6);
        #pragma unroll
        for (int ks = 0; ks < 2; ks++) {
            uint32_t af[4][4], bg[2][4];
            const uint32_t ac = (uint32_t)((((ks << 1) + acs) ^ aswz) << 4);
            const uint32_t bc = (uint32_t)((((ks << 1) + bcs) ^ bswz) << 4);
            #pragma unroll
            for (int mf = 0; mf < 4; mf++)
                LDM_X4(af[mf], abase + (uint32_t)(mf << 10) + ac);
            #pragma unroll
            for (int np = 0; np < 2; np++)
                LDM_X4(bg[np], bbase + (uint32_t)(np << 10) + bc);
            #pragma unroll
            for (int mf = 0; mf < 4; mf++)
                #pragma unroll
                for (int nf = 0; nf < 4; nf++)
                    MMA_BF16(acc[mf][nf], af[mf],
                             bg[nf >> 1][(nf & 1) << 1], bg[nf >> 1][((nf & 1) << 1) + 1]);
        }
    };

    issue(0); CP_COMMIT();
    issue(1); CP_COMMIT();
    issue(2); CP_COMMIT();
    for (int t = 0; t < 32; t++) {
        CP_WAIT2();
        __syncthreads();
        compute(t & 3);
        if (t + 3 < 32) issue(t + 3);
        CP_COMMIT();
    }

    // ---- epilogue ----------------------------------------------------------
    const int cbase = n0 + (wn << 5);
    float2 bv[4];
    #pragma unroll
    for (int nf = 0; nf < 4; nf++)
        bv[nf] = *(const float2*)(bias + cbase + (nf << 3) + ((lane & 3) << 1));
    #pragma unroll
    for (int mf = 0; mf < 4; mf++)
        #pragma unroll
        for (int nf = 0; nf < 4; nf++) {
            acc[mf][nf][0] += bv[nf].x; acc[mf][nf][1] += bv[nf].y;
            acc[mf][nf][2] += bv[nf].x; acc[mf][nf][3] += bv[nf].y;
        }

    if (MODE == 1) {
        // row softmax over the 64-col head (this warp + partner wn^1), *SCALE.
        float* sred = (float*)sm;        // [wm*4+wn][2][64] floats = 4KB
        const int me = (wm << 2) + wn, pr = (wm << 2) + (wn ^ 1);
        #pragma unroll
        for (int mf = 0; mf < 4; mf++)
            #pragma unroll
            for (int half = 0; half < 2; half++) {
                float mx = acc[mf][0][half * 2];
                #pragma unroll
                for (int nf = 0; nf < 4; nf++) {
                    mx = fmaxf(mx, acc[mf][nf][half * 2]);
                    mx = fmaxf(mx, acc[mf][nf][half * 2 + 1]);
                }
                mx = fmaxf(mx, __shfl_xor_sync(0xffffffffu, mx, 1));
                mx = fmaxf(mx, __shfl_xor_sync(0xffffffffu, mx, 2));
                if ((lane & 3) == 0)
                    sred[(me * 2 + 0) * 64 + (mf << 4) + (lane >> 2) + half * 8] = mx;
            }
        __syncthreads();
        #pragma unroll
        for (int mf = 0; mf < 4; mf++)
            #pragma unroll
            for (int half = 0; half < 2; half++) {
                const int row = (mf << 4) + (lane >> 2) + half * 8;
                const float m = fmaxf(sred[(me * 2 + 0) * 64 + row],
                                      sred[(pr * 2 + 0) * 64 + row]);
                float s = 0.f;
                #pragma unroll
                for (int nf = 0; nf < 4; nf++) {
                    acc[mf][nf][half * 2]     = __expf(acc[mf][nf][half * 2]     - m);
                    acc[mf][nf][half * 2 + 1] = __expf(acc[mf][nf][half * 2 + 1] - m);
                    s += acc[mf][nf][half * 2] + acc[mf][nf][half * 2 + 1];
                }
                s += __shfl_xor_sync(0xffffffffu, s, 1);
                s += __shfl_xor_sync(0xffffffffu, s, 2);
                if ((lane & 3) == 0) sred[(me * 2 + 1) * 64 + row] = s;
            }
        __syncthreads();
        #pragma unroll
        for (int mf = 0; mf < 4; mf++)
            #pragma unroll
            for (int half = 0; half < 2; half++) {
                const int row = (mf << 4) + (lane >> 2) + half * 8;
                const float s = sred[(me * 2 + 1) * 64 + row] +
                                sred[(pr * 2 + 1) * 64 + row];
                const float inv = SCALE / s;
                #pragma unroll
                for (int nf = 0; nf < 4; nf++) {
                    acc[mf][nf][half * 2]     *= inv;
                    acc[mf][nf][half * 2 + 1] *= inv;
                }
            }
    }

    #pragma unroll
    for (int mf = 0; mf < 4; mf++) {
        const int r0 = m0 + (wm << 6) + (mf << 4) + (lane >> 2);
        #pragma unroll
        for (int nf = 0; nf < 4; nf++) {
            const int co = (nf << 3) + ((lane & 3) << 1);
            if (MODE != 2) {
                float* Cp = C + (long long)r0 * DD + cbase + co;
                *(float2*)Cp             = make_float2(acc[mf][nf][0], acc[mf][nf][1]);
                *(float2*)(Cp + 8LL*DD)  = make_float2(acc[mf][nf][2], acc[mf][nf][3]);
            }
            if (MODE != 0) {
                const int w = (cbase >> 1) + (nf << 2) + (lane & 3);
                Cb[(size_t)r0 * DW + w]       = pack2(acc[mf][nf][0], acc[mf][nf][1]);
                Cb[(size_t)(r0 + 8) * DW + w] = pack2(acc[mf][nf][2], acc[mf][nf][3]);
            }
        }
    }
}

// ---------------------------------------------------------------------------
// pack_w: W[k][n] -> Wtb[n][k/2] packed bf16 (transpose + pack)
// ---------------------------------------------------------------------------
__global__ void __launch_bounds__(256) pack_w(const float* __restrict__ W,
                                              uint32_t* __restrict__ Wtb)
{
    __shared__ float s[64][36];
    const int n0 = blockIdx.x << 5, k0 = blockIdx.y << 6;
    const int tid = threadIdx.x;
    {
        const int i = tid >> 2, j8 = (tid & 3) << 3;
        *(float4*)&s[i][j8]     = *(const float4*)(W + (size_t)(k0 + i) * DD + n0 + j8);
        *(float4*)&s[i][j8 + 4] = *(const float4*)(W + (size_t)(k0 + i) * DD + n0 + j8 + 4);
    }
    __syncthreads();
    const int nl = tid >> 3, kg = tid & 7;
    uint4 o;
    o.x = pack2(s[kg * 8 + 0][nl], s[kg * 8 + 1][nl]);
    o.y = pack2(s[kg * 8 + 2][nl], s[kg * 8 + 3][nl]);
    o.z = pack2(s[kg * 8 + 4][nl], s[kg * 8 + 5][nl]);
    o.w = pack2(s[kg * 8 + 6][nl], s[kg * 8 + 7][nl]);
    *(uint4*)(Wtb + (size_t)(n0 + nl) * DW + (k0 >> 1) + (kg << 2)) = o;
}

// ---------------------------------------------------------------------------
// pack_rows: fp32 row-major -> packed bf16
// ---------------------------------------------------------------------------
__global__ void __launch_bounds__(256) pack_rows(const float* __restrict__ src,
                                                 uint32_t* __restrict__ dst)
{
    const size_t q = ((size_t)blockIdx.x * 256 + threadIdx.x) << 3;
    float4 a = *(const float4*)(src + q), b = *(const float4*)(src + q + 4);
    uint4 o = {pack2(a.x, a.y), pack2(a.z, a.w), pack2(b.x, b.y), pack2(b.z, b.w)};
    *(uint4*)(dst + (q >> 1)) = o;
}

// ---------------------------------------------------------------------------
// Column softmax over seq dim N -> packed bf16 g_KmB.  32 cols/CTA.
// ---------------------------------------------------------------------------
__global__ void __launch_bounds__(512) col_softmax()
{
    const int b  = blockIdx.y;
    const int c0 = blockIdx.x << 5;
    const int tx = threadIdx.x & 7;
    const int ty = threadIdx.x >> 3;
    const float* src = g_Q + (size_t)b * NN * DD + c0 + (tx << 2);
    uint32_t*    dst = g_KmB + (size_t)b * NN * DW + (c0 >> 1) + (tx << 1);

    __shared__ float4 red[64][8];

    float4 m4 = {-1e30f, -1e30f, -1e30f, -1e30f};
    for (int n = ty; n < NN; n += 64) {
        float4 v = *(const float4*)(src + (size_t)n * DD);
        m4.x = fmaxf(m4.x, v.x); m4.y = fmaxf(m4.y, v.y);
        m4.z = fmaxf(m4.z, v.z); m4.w = fmaxf(m4.w, v.w);
    }
    red[ty][tx] = m4;
    __syncthreads();
    m4 = red[0][tx];
    #pragma unroll 8
    for (int i = 1; i < 64; i++) {
        float4 r = red[i][tx];
        m4.x = fmaxf(m4.x, r.x); m4.y = fmaxf(m4.y, r.y);
        m4.z = fmaxf(m4.z, r.z); m4.w = fmaxf(m4.w, r.w);
    }
    __syncthreads();

    float4 s4 = {0.f, 0.f, 0.f, 0.f};
    for (int n = ty; n < NN; n += 64) {
        float4 v = *(const float4*)(src + (size_t)n * DD);
        s4.x += __expf(v.x - m4.x); s4.y += __expf(v.y - m4.y);
        s4.z += __expf(v.z - m4.z); s4.w += __expf(v.w - m4.w);
    }
    red[ty][tx] = s4;
    __syncthreads();
    s4.x = 0.f; s4.y = 0.f; s4.z = 0.f; s4.w = 0.f;
    #pragma unroll 8
    for (int i = 0; i < 64; i++) {
        float4 r = red[i][tx];
        s4.x += r.x; s4.y += r.y; s4.z += r.z; s4.w += r.w;
    }
    const float4 inv = {SCALE / s4.x, SCALE / s4.y, SCALE / s4.z, SCALE / s4.w};

    for (int n = ty; n < NN; n += 64) {
        float4 v = *(const float4*)(src + (size_t)n * DD);
        uint2 o;
        o.x = pack2(__expf(v.x - m4.x) * inv.x, __expf(v.y - m4.y) * inv.y);
        o.y = pack2(__expf(v.z - m4.z) * inv.z, __expf(v.w - m4.w) * inv.w);
        *(uint2*)(dst + (size_t)n * DW) = o;
    }
}

// ---------------------------------------------------------------------------
// ctx via tensor cores: ctx[sp][bh][d][e] = sum_{n in slice} Km[n,d]*V[n,e]
// Km, V packed bf16 [n][feat]; trans-ldmatrix gives Km^T (A) and V^T (B).
// Grid (64, CTXSP), 256 thr = 8 warps: wd=wid>>1 (d16), we=wid&1 (e32).
// Stage: 32 n-rows x 64 feat per operand (4KB each), 4-stage cp.async.
// ---------------------------------------------------------------------------
__global__ void __launch_bounds__(256) ctx_mma()
{
    __shared__ uint32_t cs[4][2048];   // 32KB: per stage [Km 1024w | V 1024w]
    const int bh = blockIdx.x, b = bh >> 4, h = bh & 15;
    const int n0 = blockIdx.y << 11;   // 2048 rows per split
    const int tid = threadIdx.x, lane = tid & 31, wid = tid >> 5;
    const int wd = wid >> 1, we = wid & 1;
    const uint32_t sbase = smem_u32(cs);

    const uint32_t* KmP = g_KmB + (size_t)b * NN * DW + h * 32;
    const uint32_t* VbP = g_Vb  + (size_t)b * NN * DW + h * 32;

    const int lop = tid >> 7, t7 = tid & 127;
    const int lrow = t7 >> 2, lc2 = (t7 & 3) << 1;
    const uint32_t* lsrc = (lop ? VbP : KmP) + (size_t)(n0 + lrow) * DW;
    const uint32_t d0 = sbase + (((lop << 10) + lrow * 32 + ((lc2       ^ (lrow & 7)) << 2)) << 2);
    const uint32_t d1 = sbase + (((lop << 10) + lrow * 32 + (((lc2 + 1) ^ (lrow & 7)) << 2)) << 2);

    auto issue = [&](int t) {          // k-chunk t -> stage t&3
        const uint32_t so = (uint32_t)(t & 3) << 13;
        const uint32_t* s = lsrc + (size_t)(t << 5) * DW;
        CP_ASYNC16(d0 + so, s + (lc2 << 2));
        CP_ASYNC16(d1 + so, s + ((lc2 + 1) << 2));
    };

    // A (Km^T): rows n = (lane&7)|((lane&16)>>1), d-half sel (lane>>3)&1
    const int arow = (lane & 7) | ((lane & 16) >> 1);
    const int achk = (wd << 1) + ((lane >> 3) & 1);
    // B (V^T): rows n = lane&15, e-half sel lane>>4
    const int brow = lane & 15;

    float acc[4][4];
    #pragma unroll
    for (int i = 0; i < 4; i++)
        #pragma unroll
        for (int j = 0; j < 4; j++) acc[i][j] = 0.f;

    auto compute = [&](int stg) {
        const uint32_t so = (uint32_t)stg << 13;
        #pragma unroll
        for (int ks = 0; ks < 2; ks++) {
            uint32_t af[4], bg[2][4];
            {
                const int r = (ks << 4) + arow;
                LDM_X4T(af, sbase + so + ((r * 32 + ((achk ^ (r & 7)) << 2)) << 2));
            }
            #pragma unroll
            for (int np = 0; np < 2; np++) {
                const int r = (ks << 4) + brow;
                const int c = (we << 2) + (np << 1) + (lane >> 4);
                LDM_X4T(bg[np], sbase + so + ((1024 + r * 32 + ((c ^ (r & 7)) << 2)) << 2));
            }
            #pragma unroll
            for (int nf = 0; nf < 4; nf++)
                MMA_BF16(acc[nf], af,
                         bg[nf >> 1][(nf & 1) << 1], bg[nf >> 1][((nf & 1) << 1) + 1]);
        }
    };

    issue(0); CP_COMMIT();
    issue(1); CP_COMMIT();
    issue(2); CP_COMMIT();
    for (int t = 0; t < 64; t++) {
        CP_WAIT2();
        __syncthreads();
        compute(t & 3);
        if (t + 3 < 64) issue(t + 3);
        CP_COMMIT();
    }

    float* o = g_ctx + (((size_t)blockIdx.y * (BB * HH) + bh) << 12);
    const int d = (wd << 4) + (lane >> 2);
    #pragma unroll
    for (int nf = 0; nf < 4; nf++) {
        const int e = (we << 5) + (nf << 3) + ((lane & 3) << 1);
        *(float2*)(o + d * 64 + e)       = make_float2(acc[nf][0], acc[nf][1]);
        *(float2*)(o + (d + 8) * 64 + e) = make_float2(acc[nf][2], acc[nf][3]);
    }
}

// ---------------------------------------------------------------------------
// Mbig^T packed: g_Mtb[b][n][k/2] = pack(sum_e ctx[b,h][d][e]*Wo[h*64+e][n])
// ---------------------------------------------------------------------------
__global__ void __launch_bounds__(256) mbig_kernel(const float* __restrict__ Wo)
{
    const int bh = blockIdx.x, b = bh >> 4, h = bh & 15;
    const int c0 = blockIdx.y << 6;

    __shared__ float csx[64][64];
    __shared__ float ws[64][64];
    const int tid = threadIdx.x;

    for (int i = tid; i < 4096; i += 256) {
        float sum = 0.f;
        #pragma unroll
        for (int sp = 0; sp < CTXSP; sp++)
            sum += g_ctx[(((size_t)sp * (BB * HH) + bh) << 12) + i];
        csx[i >> 6][i & 63] = sum;
    }
    for (int i = tid; i < 1024; i += 256) {
        int rr = i >> 4, cc = (i & 15) << 2;
        *(float4*)&ws[rr][cc] =
            *(const float4*)(Wo + (size_t)(h * DH + rr) * DD + c0 + cc);
    }
    __syncthreads();

    const int r0 = (tid >> 4) << 2, cc0 = (tid & 15) << 2;
    float acc[4][4] = {};
    #pragma unroll 16
    for (int k = 0; k < 64; k++) {
        float a[4], w[4];
        #pragma unroll
        for (int i = 0; i < 4; i++) a[i] = csx[r0 + i][k];
        *(float4*)w = *(float4*)&ws[k][cc0];
        #pragma unroll
        for (int i = 0; i < 4; i++)
            #pragma unroll
            for (int j = 0; j < 4; j++)
                acc[i][j] = fmaf(a[i], w[j], acc[i][j]);
    }
    uint32_t* ob = g_Mtb + ((size_t)b * DD * DW);
    const int kb2 = (h * DH + r0) >> 1;
    #pragma unroll
    for (int j = 0; j < 4; j++) {
        const size_t n = (size_t)(c0 + cc0 + j);
        ob[n * DW + kb2]     = pack2(acc[0][j], acc[1][j]);
        ob[n * DW + kb2 + 1] = pack2(acc[2][j], acc[3][j]);
    }
}

// ---------------------------------------------------------------------------
// Launcher. Inputs: 0:x 1:Wq 2:bq 3:Wk(dead) 4:bk(dead) 5:Wv 6:bv 7:Wo 8:bo
// ---------------------------------------------------------------------------
extern "C" void kernel_launch(void* const* d_in, const int* in_sizes, int n_in,
                              void* d_out, int out_size)
{
    const float* x  = (const float*)d_in[0];
    const float* Wq = (const float*)d_in[1];
    const float* bq = (const float*)d_in[2];
    const float* Wv = (const float*)d_in[5];
    const float* bv = (const float*)d_in[6];
    const float* Wo = (const float*)d_in[7];
    const float* bo = (const float*)d_in[8];
    float* out = (float*)d_out;

    float* Q;
    uint32_t *xb, *Qb, *Vb, *Wqb, *Wvb, *Mtb;
    cudaGetSymbolAddress((void**)&Q,   g_Q);
    cudaGetSymbolAddress((void**)&xb,  g_xb);
    cudaGetSymbolAddress((void**)&Qb,  g_Qb);
    cudaGetSymbolAddress((void**)&Vb,  g_Vb);
    cudaGetSymbolAddress((void**)&Wqb, g_Wqb);
    cudaGetSymbolAddress((void**)&Wvb, g_Wvb);
    cudaGetSymbolAddress((void**)&Mtb, g_Mtb);

    cudaFuncSetAttribute((const void*)gemm_bf16<0>,
                         cudaFuncAttributeMaxDynamicSharedMemorySize, GEMM_SMEM);
    cudaFuncSetAttribute((const void*)gemm_bf16<1>,
                         cudaFuncAttributeMaxDynamicSharedMemorySize, GEMM_SMEM);
    cudaFuncSetAttribute((const void*)gemm_bf16<2>,
                         cudaFuncAttributeMaxDynamicSharedMemorySize, GEMM_SMEM);

    const long long sXW = (long long)NN * DW;
    const long long sXD = (long long)NN * DD;
    dim3 ggrid(DD / 128, NN / 128, BB);

    pack_rows<<<(BB * NN * DD) / (256 * 8), 256>>>(x, xb);
    pack_w<<<dim3(DD / 32, DD / 64), 256>>>(Wq, Wqb);
    pack_w<<<dim3(DD / 32, DD / 64), 256>>>(Wv, Wvb);

    // Q = softmax(x@Wq + bq) * s  (fused epilogue; fp32 + packed)
    gemm_bf16<1><<<ggrid, 256, GEMM_SMEM>>>(xb, Wqb, bq, Q, Qb, sXW, 0, sXD);
    // V = x@Wv + bv  (packed bf16 only)
    gemm_bf16<2><<<ggrid, 256, GEMM_SMEM>>>(xb, Wvb, bv, Q, Vb, sXW, 0, sXD);

    // Km = softmax(Qs, seq) * s  (packed bf16)
    col_softmax<<<dim3(DD / 32, BB), 512>>>();

    // ctx partials (tensor cores), then Mbig^T packed
    ctx_mma<<<dim3(BB * HH, CTXSP), 256>>>();
    mbig_kernel<<<dim3(BB * HH, DD / 64), 256>>>(Wo);

    // out[b] = Qs[b] @ Mbig[b] + bo
    gemm_bf16<0><<<ggrid, 256, GEMM_SMEM>>>(Qb, Mtb, bo, out, Qb,
                                            sXW, (long long)DD * DW, sXD);
}